// round 1
// baseline (speedup 1.0000x reference)
#include <cuda_runtime.h>
#include <cuda_bf16.h>

#define NB 2
#define NC 256
#define NL 4096

// Scratch (device globals: allowed; no allocation in kernel_launch)
__device__ float g_q [NB * NC * NL];          // normalized trg, [B][C][L]
__device__ float g_ks[NB * NC * NL];          // normalized src
__device__ float g_kr[NB * NC * NL];          // normalized ref
__device__ float g_p [4ull * NL * NL];        // [z = type*2 + b][L][L] corr -> attn

// ---------------------------------------------------------------------------
// Kernel 1: channel mean-subtract + L2 normalize, per spatial position.
// Layout stays [B][C][L]; per-thread column walk, coalesced across threads.
// ---------------------------------------------------------------------------
__global__ void __launch_bounds__(256) norm_kernel(const float* __restrict__ trg,
                                                   const float* __restrict__ src,
                                                   const float* __restrict__ ref) {
    const int which = blockIdx.z;
    const float* x = (which == 0) ? trg : (which == 1) ? src : ref;
    float* y       = (which == 0) ? g_q : (which == 1) ? g_ks : g_kr;

    const int b = blockIdx.y;
    const int l = blockIdx.x * blockDim.x + threadIdx.x;

    const float* xp = x + (size_t)b * NC * NL + l;
    float* yp       = y + (size_t)b * NC * NL + l;

    float sum = 0.f, sumsq = 0.f;
#pragma unroll 8
    for (int c = 0; c < NC; c++) {
        float v = xp[(size_t)c * NL];
        sum += v;
        sumsq += v * v;
    }
    const float mean = sum * (1.0f / NC);
    // sum_c (x-mean)^2 = sumsq - sum*mean
    const float inv = rsqrtf(fmaxf(sumsq - sum * mean, 1e-30f));
#pragma unroll 8
    for (int c = 0; c < NC; c++) {
        yp[(size_t)c * NL] = (xp[(size_t)c * NL] - mean) * inv;
    }
}

// ---------------------------------------------------------------------------
// Kernel 2: corr[z][i][j] = sum_c Q[b][c][i] * K[b][c][j]   (z = type*2 + b)
// Both operands are [C][L] (N-major) -> TN GEMM, tiles load with contiguous
// leading dim, no smem transpose. 128x128 block tile, BK=8, 8x8 per thread.
// ---------------------------------------------------------------------------
__global__ void __launch_bounds__(256) corr_kernel() {
    const int z = blockIdx.z;
    const int b = z & 1;
    const int type = z >> 1;
    const float* __restrict__ A = g_q + (size_t)b * NC * NL;
    const float* __restrict__ Bm = (type ? g_kr : g_ks) + (size_t)b * NC * NL;
    float* __restrict__ Cm = g_p + (size_t)z * NL * NL;

    __shared__ float As[8][128];
    __shared__ float Bs[8][128];

    const int tid = threadIdx.x;
    const int tx = tid & 15;        // 0..15 -> col group
    const int ty = tid >> 4;        // 0..15 -> row group
    const int i0 = blockIdx.x * 128;
    const int j0 = blockIdx.y * 128;

    const int lr = tid >> 5;          // 0..7  (k row in tile)
    const int lc = (tid & 31) << 2;   // 0..124 (float4 col)

    const float* Ald = A + (size_t)lr * NL + i0 + lc;
    const float* Bld = Bm + (size_t)lr * NL + j0 + lc;

    float acc[8][8];
#pragma unroll
    for (int m = 0; m < 8; m++)
#pragma unroll
        for (int n = 0; n < 8; n++) acc[m][n] = 0.f;

    for (int k0 = 0; k0 < NC; k0 += 8) {
        float4 av = *(const float4*)Ald;
        float4 bv = *(const float4*)Bld;
        Ald += (size_t)8 * NL;
        Bld += (size_t)8 * NL;
        *(float4*)&As[lr][lc] = av;
        *(float4*)&Bs[lr][lc] = bv;
        __syncthreads();

#pragma unroll
        for (int kk = 0; kk < 8; kk++) {
            float a[8], bb[8];
            *(float4*)(a)     = *(const float4*)&As[kk][ty * 8];
            *(float4*)(a + 4) = *(const float4*)&As[kk][ty * 8 + 4];
            *(float4*)(bb)     = *(const float4*)&Bs[kk][tx * 8];
            *(float4*)(bb + 4) = *(const float4*)&Bs[kk][tx * 8 + 4];
#pragma unroll
            for (int m = 0; m < 8; m++)
#pragma unroll
                for (int n = 0; n < 8; n++)
                    acc[m][n] = fmaf(a[m], bb[n], acc[m][n]);
        }
        __syncthreads();
    }

#pragma unroll
    for (int m = 0; m < 8; m++) {
        float* cp = Cm + (size_t)(i0 + ty * 8 + m) * NL + j0 + tx * 8;
        *(float4*)cp       = make_float4(acc[m][0], acc[m][1], acc[m][2], acc[m][3]);
        *(float4*)(cp + 4) = make_float4(acc[m][4], acc[m][5], acc[m][6], acc[m][7]);
    }
}

// ---------------------------------------------------------------------------
// Kernel 3: in-place row softmax over j. One block per row; row cached in smem.
// ---------------------------------------------------------------------------
__global__ void __launch_bounds__(256) softmax_kernel() {
    const int z = blockIdx.y;
    const int i = blockIdx.x;
    float* __restrict__ row = g_p + (size_t)z * NL * NL + (size_t)i * NL;

    __shared__ float buf[NL];
    __shared__ float sred[8];

    const int tid = threadIdx.x;

    // Load + local max
    float mx = -1e30f;
#pragma unroll
    for (int t = 0; t < 4; t++) {
        const int e = (t * 256 + tid) * 4;
        float4 v = *(const float4*)&row[e];
        *(float4*)&buf[e] = v;
        mx = fmaxf(mx, fmaxf(fmaxf(v.x, v.y), fmaxf(v.z, v.w)));
    }
#pragma unroll
    for (int o = 16; o > 0; o >>= 1) mx = fmaxf(mx, __shfl_xor_sync(0xffffffffu, mx, o));
    if ((tid & 31) == 0) sred[tid >> 5] = mx;
    __syncthreads();
    if (tid == 0) {
        float r = sred[0];
#pragma unroll
        for (int w = 1; w < 8; w++) r = fmaxf(r, sred[w]);
        sred[0] = r;
    }
    __syncthreads();
    mx = sred[0];
    __syncthreads();

    // exp + local sum
    float s = 0.f;
#pragma unroll
    for (int t = 0; t < 4; t++) {
        const int e = (t * 256 + tid) * 4;
        float4 v = *(const float4*)&buf[e];
        v.x = __expf(v.x - mx);
        v.y = __expf(v.y - mx);
        v.z = __expf(v.z - mx);
        v.w = __expf(v.w - mx);
        *(float4*)&buf[e] = v;
        s += v.x + v.y + v.z + v.w;
    }
#pragma unroll
    for (int o = 16; o > 0; o >>= 1) s += __shfl_xor_sync(0xffffffffu, s, o);
    if ((tid & 31) == 0) sred[tid >> 5] = s;
    __syncthreads();
    if (tid == 0) {
        float r = 0.f;
#pragma unroll
        for (int w = 0; w < 8; w++) r += sred[w];
        sred[0] = r;
    }
    __syncthreads();
    const float inv = 1.0f / sred[0];

#pragma unroll
    for (int t = 0; t < 4; t++) {
        const int e = (t * 256 + tid) * 4;
        float4 v = *(const float4*)&buf[e];
        v.x *= inv; v.y *= inv; v.z *= inv; v.w *= inv;
        *(float4*)&row[e] = v;
    }
}

// ---------------------------------------------------------------------------
// Kernel 4: out[c][i] = sum_j P[i][j] * V[c][j]. BM=64 rows, all channels in
// one pass (P read exactly once). 16x16 threads, TM=4 rows, 10 channel slots.
// ---------------------------------------------------------------------------
#define GBM 64
#define GBK 32
#define CPAD 165

__global__ void __launch_bounds__(256) gather_kernel(const float* __restrict__ src_feats,
                                                     const float* __restrict__ ref_feats,
                                                     const float* __restrict__ ref_sem,
                                                     float* __restrict__ out) {
    const int z = blockIdx.z;
    const int b = z & 1;
    const int type = z >> 1;
    const float* __restrict__ P = g_p + (size_t)z * NL * NL;

    const int nch = type ? 155 : 4;
    const float* Vf = (type ? ref_feats : src_feats) + (size_t)b * 4 * NL;
    const float* Vs2 = ref_sem + (size_t)b * 151 * NL;
    float* Of = type ? (out + 2 * 4 * NL + (size_t)b * 4 * NL)
                     : (out + (size_t)b * 4 * NL);
    float* Os = out + 4 * 4 * NL + (size_t)b * 151 * NL;

    __shared__ float Ps[GBM][36];          // pad 36: float4-aligned, conflict-shifted
    __shared__ float Vsm[GBK * CPAD];      // [kk][c], pad 165 (gcd(165,32)=1)

    const int tid = threadIdx.x;
    const int tx = tid & 15;
    const int ty = tid >> 4;
    const int i0 = blockIdx.x * GBM;

    float acc[4][10];
#pragma unroll
    for (int m = 0; m < 4; m++)
#pragma unroll
        for (int s = 0; s < 10; s++) acc[m][s] = 0.f;

    for (int j0 = 0; j0 < NL; j0 += GBK) {
        // P tile: 64x32 floats = 512 float4, 2 per thread
#pragma unroll
        for (int t = 0; t < 2; t++) {
            const int idx = tid + t * 256;
            const int r = idx >> 3;
            const int s4 = (idx & 7) << 2;
            float4 v = *(const float4*)&P[(size_t)(i0 + r) * NL + j0 + s4];
            *(float4*)&Ps[r][s4] = v;
        }
        // V tile: nch x 32
        for (int idx = tid; idx < nch * GBK; idx += 256) {
            const int c = idx >> 5;
            const int kk = idx & 31;
            const float* vp = (c < 4) ? (Vf + (size_t)c * NL) : (Vs2 + (size_t)(c - 4) * NL);
            Vsm[kk * CPAD + c] = vp[j0 + kk];
        }
        __syncthreads();

#pragma unroll
        for (int kk = 0; kk < GBK; kk++) {
            float pv[4];
#pragma unroll
            for (int m = 0; m < 4; m++) pv[m] = Ps[ty * 4 + m][kk];
#pragma unroll
            for (int s = 0; s < 10; s++) {
                const int c = tx + s * 16;
                if (c < nch) {
                    const float v = Vsm[kk * CPAD + c];
#pragma unroll
                    for (int m = 0; m < 4; m++) acc[m][s] = fmaf(pv[m], v, acc[m][s]);
                }
            }
        }
        __syncthreads();
    }

#pragma unroll
    for (int s = 0; s < 10; s++) {
        const int c = tx + s * 16;
        if (c < nch) {
            float* op = (c < 4) ? (Of + (size_t)c * NL) : (Os + (size_t)(c - 4) * NL);
#pragma unroll
            for (int m = 0; m < 4; m++) op[i0 + ty * 4 + m] = acc[m][s];
        }
    }
}

// ---------------------------------------------------------------------------
extern "C" void kernel_launch(void* const* d_in, const int* in_sizes, int n_in,
                              void* d_out, int out_size) {
    const float* trg       = (const float*)d_in[0];
    const float* src       = (const float*)d_in[1];
    const float* ref       = (const float*)d_in[2];
    const float* src_feats = (const float*)d_in[3];
    const float* ref_feats = (const float*)d_in[4];
    const float* ref_sem   = (const float*)d_in[5];
    float* out = (float*)d_out;

    norm_kernel<<<dim3(NL / 256, NB, 3), 256>>>(trg, src, ref);
    corr_kernel<<<dim3(NL / 128, NL / 128, 4), 256>>>();
    softmax_kernel<<<dim3(NL, 4), 256>>>();
    gather_kernel<<<dim3(NL / GBM, 1, 4), 256>>>(src_feats, ref_feats, ref_sem, out);
}

// round 3
// speedup vs baseline: 3.4678x; 3.4678x over previous
#include <cuda_runtime.h>
#include <cstdint>

#define NB 2
#define NC 256
#define NL 4096

// ---------------------------------------------------------------------------
// Scratch
// ---------------------------------------------------------------------------
__device__ float g_q [NB * NL * NC];        // normalized trg, [B][L][C] K-major, tf32
__device__ float g_ks[NB * NL * NC];
__device__ float g_kr[NB * NL * NC];
__device__ float g_v [4ull * 160 * NL];     // padded V banks per z, tf32
__device__ float g_p [4ull * NL * NL];      // corr -> attn (tf32 after softmax)

// ---------------------------------------------------------------------------
// helpers
// ---------------------------------------------------------------------------
__device__ __forceinline__ uint32_t smem_u32(const void* p) {
    uint32_t a;
    asm("{ .reg .u64 t; cvta.to.shared.u64 t, %1; cvt.u32.u64 %0, t; }" : "=r"(a) : "l"(p));
    return a;
}
__device__ __forceinline__ float to_tf32(float x) {
    float r;
    asm("cvt.rna.tf32.f32 %0, %1;" : "=f"(r) : "f"(x));
    return r;
}

#define CPA16(dst, src) asm volatile("cp.async.cg.shared.global [%0], [%1], 16;" :: "r"(dst), "l"(src))
#define CPCOMMIT()      asm volatile("cp.async.commit_group;" ::: "memory")
#define CPWAIT(n)       asm volatile("cp.async.wait_group %0;" :: "n"(n) : "memory")

// smem tile index: rows of 32 floats, 4-float groups XOR-swizzled by row -> conflict-free
__device__ __forceinline__ int swz(int m, int f, int q) {
    return (m << 5) + (((f) ^ (m & 7)) << 2) + q;
}

__device__ __forceinline__ void mma8(float* d, const uint32_t* a, uint32_t b0, uint32_t b1) {
    asm volatile(
        "mma.sync.aligned.m16n8k8.row.col.f32.tf32.tf32.f32 "
        "{%0,%1,%2,%3}, {%4,%5,%6,%7}, {%8,%9}, {%0,%1,%2,%3};"
        : "+f"(d[0]), "+f"(d[1]), "+f"(d[2]), "+f"(d[3])
        : "r"(a[0]), "r"(a[1]), "r"(a[2]), "r"(a[3]), "r"(b0), "r"(b1));
}

// ---------------------------------------------------------------------------
// Kernel 1: normalize -> [B][L][C] K-major, tf32-rounded
// ---------------------------------------------------------------------------
__global__ void __launch_bounds__(256) norm_kernel(const float* __restrict__ trg,
                                                   const float* __restrict__ src,
                                                   const float* __restrict__ ref) {
    const int which = blockIdx.z;
    const float* x = (which == 0) ? trg : (which == 1) ? src : ref;
    float* y       = (which == 0) ? g_q : (which == 1) ? g_ks : g_kr;

    const int b = blockIdx.y;
    const int l0 = blockIdx.x * 32;
    const int t = threadIdx.x;
    const int l = t & 31;
    const int cg = t >> 5;

    __shared__ float buf[32][257];
    __shared__ float red[2][8][32];
    __shared__ float mi[2][32];

    const float* xb = x + (size_t)b * NC * NL + l0 + l;

    float s = 0.f, q = 0.f;
#pragma unroll 8
    for (int cc = 0; cc < 32; cc++) {
        const int c = cg * 32 + cc;
        float v = xb[(size_t)c * NL];
        buf[l][c] = v;
        s += v;
        q += v * v;
    }
    red[0][cg][l] = s;
    red[1][cg][l] = q;
    __syncthreads();

    if (t < 32) {
        float su = 0.f, ss = 0.f;
#pragma unroll
        for (int w = 0; w < 8; w++) { su += red[0][w][t]; ss += red[1][w][t]; }
        const float mean = su * (1.0f / NC);
        mi[0][t] = mean;
        mi[1][t] = rsqrtf(fmaxf(ss - su * mean, 1e-30f));
    }
    __syncthreads();

    const float mean = mi[0][l];
    const float inv = mi[1][l];
#pragma unroll 8
    for (int cc = 0; cc < 32; cc++) {
        const int c = cg * 32 + cc;
        buf[l][c] = to_tf32((buf[l][c] - mean) * inv);
    }
    __syncthreads();

    float* yb = y + (size_t)b * NL * NC + (size_t)l0 * NC;
#pragma unroll 8
    for (int r = 0; r < 32; r++) {
        yb[(size_t)r * NC + t] = buf[r][t];
    }
}

// ---------------------------------------------------------------------------
// Kernel 1b: build padded tf32 V banks. z<2: rows 0..7 (4 feats + 0s).
//            z>=2: rows 0..159 (4 feats, 151 sem, 5 zeros).
// ---------------------------------------------------------------------------
__global__ void __launch_bounds__(256) vprep_kernel(const float* __restrict__ sf,
                                                    const float* __restrict__ rf,
                                                    const float* __restrict__ rs) {
    const int z = blockIdx.z, b = z & 1, type = z >> 1;
    const int n = blockIdx.y;
    if (!type && n >= 8) return;
    const int l = blockIdx.x * 256 + threadIdx.x;
    float v = 0.f;
    if (n < 4) v = (type ? rf : sf)[(size_t)b * 4 * NL + (size_t)n * NL + l];
    else if (type && n < 155) v = rs[(size_t)b * 151 * NL + (size_t)(n - 4) * NL + l];
    g_v[(size_t)z * 160 * NL + (size_t)n * NL + l] = to_tf32(v);
}

// ---------------------------------------------------------------------------
// Kernel 2: corr = Q^T K via mma.sync tf32. CTA 128x128, BK=32, 2-stage cp.async.
// smem: 2 stages x (A 4096 + B 4096 floats) = 64KB dynamic.
// ---------------------------------------------------------------------------
#define CORR_SMEM 65536

__global__ void __launch_bounds__(256) corr_kernel() {
    extern __shared__ float dsm[];
    const int tid = threadIdx.x, lane = tid & 31, wid = tid >> 5;
    const int wy = wid & 3, wx = wid >> 2;
    const int z = blockIdx.z, b = z & 1, type = z >> 1;
    const int i0 = blockIdx.x * 128, j0 = blockIdx.y * 128;

    const float* __restrict__ A = g_q + (size_t)b * NL * NC;
    const float* __restrict__ B = (type ? g_kr : g_ks) + (size_t)b * NL * NC;
    float* __restrict__ Cm = g_p + (size_t)z * NL * NL;

    const uint32_t sbase = smem_u32(dsm);

    auto stage = [&](int st, int c0) {
        const uint32_t abase = sbase + (uint32_t)st * 8192u * 4u;
        const uint32_t bbase = abase + 4096u * 4u;
#pragma unroll
        for (int it = 0; it < 4; it++) {
            int idx = tid + it * 256, m = idx >> 3, f = idx & 7;
            CPA16(abase + swz(m, f, 0) * 4, A + (size_t)(i0 + m) * NC + c0 + f * 4);
        }
#pragma unroll
        for (int it = 0; it < 4; it++) {
            int idx = tid + it * 256, m = idx >> 3, f = idx & 7;
            CPA16(bbase + swz(m, f, 0) * 4, B + (size_t)(j0 + m) * NC + c0 + f * 4);
        }
    };

    float acc[2][8][4];
#pragma unroll
    for (int mt = 0; mt < 2; mt++)
#pragma unroll
        for (int nt = 0; nt < 8; nt++)
#pragma unroll
            for (int k = 0; k < 4; k++) acc[mt][nt][k] = 0.f;

    stage(0, 0); CPCOMMIT();

    const int q = lane & 3, r = lane >> 2;
    for (int c = 0; c < 8; c++) {
        if (c < 7) { stage((c + 1) & 1, (c + 1) * 32); CPCOMMIT(); CPWAIT(1); }
        else       { CPWAIT(0); }
        __syncthreads();
        const uint32_t* As = (const uint32_t*)(dsm + (c & 1) * 8192);
        const uint32_t* Bs = As + 4096;
#pragma unroll
        for (int ks = 0; ks < 4; ks++) {
            const int f0 = ks * 2;
            uint32_t a[2][4];
#pragma unroll
            for (int mt = 0; mt < 2; mt++) {
                const int m = wy * 32 + mt * 16 + r;
                a[mt][0] = As[swz(m,     f0,     q)];
                a[mt][1] = As[swz(m + 8, f0,     q)];
                a[mt][2] = As[swz(m,     f0 + 1, q)];
                a[mt][3] = As[swz(m + 8, f0 + 1, q)];
            }
#pragma unroll
            for (int nt = 0; nt < 8; nt++) {
                const int n = wx * 64 + nt * 8 + r;
                uint32_t b0 = Bs[swz(n, f0,     q)];
                uint32_t b1 = Bs[swz(n, f0 + 1, q)];
                mma8(acc[0][nt], a[0], b0, b1);
                mma8(acc[1][nt], a[1], b0, b1);
            }
        }
        __syncthreads();
    }

#pragma unroll
    for (int mt = 0; mt < 2; mt++) {
        const int row = i0 + wy * 32 + mt * 16 + r;
#pragma unroll
        for (int nt = 0; nt < 8; nt++) {
            const int col = j0 + wx * 64 + nt * 8 + 2 * q;
            *(float2*)&Cm[(size_t)row * NL + col]       = make_float2(acc[mt][nt][0], acc[mt][nt][1]);
            *(float2*)&Cm[(size_t)(row + 8) * NL + col] = make_float2(acc[mt][nt][2], acc[mt][nt][3]);
        }
    }
}

// ---------------------------------------------------------------------------
// Kernel 3: in-place row softmax, tf32-rounded probabilities
// ---------------------------------------------------------------------------
__global__ void __launch_bounds__(256) softmax_kernel() {
    const int z = blockIdx.y;
    const int i = blockIdx.x;
    float* __restrict__ row = g_p + (size_t)z * NL * NL + (size_t)i * NL;

    __shared__ float buf[NL];
    __shared__ float sred[8];

    const int tid = threadIdx.x;

    float mx = -1e30f;
#pragma unroll
    for (int t = 0; t < 4; t++) {
        const int e = (t * 256 + tid) * 4;
        float4 v = *(const float4*)&row[e];
        *(float4*)&buf[e] = v;
        mx = fmaxf(mx, fmaxf(fmaxf(v.x, v.y), fmaxf(v.z, v.w)));
    }
#pragma unroll
    for (int o = 16; o > 0; o >>= 1) mx = fmaxf(mx, __shfl_xor_sync(0xffffffffu, mx, o));
    if ((tid & 31) == 0) sred[tid >> 5] = mx;
    __syncthreads();
    if (tid == 0) {
        float r = sred[0];
#pragma unroll
        for (int w = 1; w < 8; w++) r = fmaxf(r, sred[w]);
        sred[0] = r;
    }
    __syncthreads();
    mx = sred[0];
    __syncthreads();

    float s = 0.f;
#pragma unroll
    for (int t = 0; t < 4; t++) {
        const int e = (t * 256 + tid) * 4;
        float4 v = *(const float4*)&buf[e];
        v.x = __expf(v.x - mx);
        v.y = __expf(v.y - mx);
        v.z = __expf(v.z - mx);
        v.w = __expf(v.w - mx);
        *(float4*)&buf[e] = v;
        s += v.x + v.y + v.z + v.w;
    }
#pragma unroll
    for (int o = 16; o > 0; o >>= 1) s += __shfl_xor_sync(0xffffffffu, s, o);
    if ((tid & 31) == 0) sred[tid >> 5] = s;
    __syncthreads();
    if (tid == 0) {
        float r = 0.f;
#pragma unroll
        for (int w = 0; w < 8; w++) r += sred[w];
        sred[0] = r;
    }
    __syncthreads();
    const float inv = 1.0f / sred[0];

#pragma unroll
    for (int t = 0; t < 4; t++) {
        const int e = (t * 256 + tid) * 4;
        float4 v = *(const float4*)&buf[e];
        v.x = to_tf32(v.x * inv);
        v.y = to_tf32(v.y * inv);
        v.z = to_tf32(v.z * inv);
        v.w = to_tf32(v.w * inv);
        *(float4*)&row[e] = v;
    }
}

// ---------------------------------------------------------------------------
// Kernel 4: gather out[c][i] = sum_j P[i][j] V[c][j]. CTA 128 rows, full N.
// ---------------------------------------------------------------------------
template <int TYPE, int NT, int WY, int WX>
__global__ void __launch_bounds__(256) gather_kernel(float* __restrict__ out) {
    constexpr int MT  = 128 / (WY * 16);   // type1: 2, type0: 1
    constexpr int NTL = NT / (WX * 8);     // type1: 10, type0: 1
    constexpr int ASZ = 128 * 32;
    constexpr int BSZ = NT * 32;

    extern __shared__ float dsm[];
    const int tid = threadIdx.x, lane = tid & 31, wid = tid >> 5;
    const int wy = wid % WY, wx = wid / WY;
    const int b = blockIdx.z, z = TYPE * 2 + b;
    const int i0 = blockIdx.x * 128;

    const float* __restrict__ P = g_p + (size_t)z * NL * NL;
    const float* __restrict__ V = g_v + (size_t)z * 160 * NL;

    const uint32_t sbase = smem_u32(dsm);

    auto stage = [&](int st, int j0) {
        const uint32_t abase = sbase + (uint32_t)st * (ASZ + BSZ) * 4u;
        const uint32_t bbase = abase + (uint32_t)ASZ * 4u;
#pragma unroll
        for (int it = 0; it < 4; it++) {
            int idx = tid + it * 256, m = idx >> 3, f = idx & 7;
            CPA16(abase + swz(m, f, 0) * 4, P + (size_t)(i0 + m) * NL + j0 + f * 4);
        }
        for (int idx = tid; idx < NT * 8; idx += 256) {
            int n = idx >> 3, f = idx & 7;
            CPA16(bbase + swz(n, f, 0) * 4, V + (size_t)n * NL + j0 + f * 4);
        }
    };

    float acc[MT][NTL][4];
#pragma unroll
    for (int mt = 0; mt < MT; mt++)
#pragma unroll
        for (int nt = 0; nt < NTL; nt++)
#pragma unroll
            for (int k = 0; k < 4; k++) acc[mt][nt][k] = 0.f;

    stage(0, 0); CPCOMMIT();

    const int q = lane & 3, r = lane >> 2;
    for (int c = 0; c < 128; c++) {
        if (c < 127) { stage((c + 1) & 1, (c + 1) * 32); CPCOMMIT(); CPWAIT(1); }
        else         { CPWAIT(0); }
        __syncthreads();
        const uint32_t* As = (const uint32_t*)(dsm + (c & 1) * (ASZ + BSZ));
        const uint32_t* Bs = As + ASZ;
#pragma unroll
        for (int ks = 0; ks < 4; ks++) {
            const int f0 = ks * 2;
            uint32_t a[MT][4];
#pragma unroll
            for (int mt = 0; mt < MT; mt++) {
                const int m = wy * (MT * 16) + mt * 16 + r;
                a[mt][0] = As[swz(m,     f0,     q)];
                a[mt][1] = As[swz(m + 8, f0,     q)];
                a[mt][2] = As[swz(m,     f0 + 1, q)];
                a[mt][3] = As[swz(m + 8, f0 + 1, q)];
            }
#pragma unroll
            for (int nt = 0; nt < NTL; nt++) {
                const int n = wx * (NTL * 8) + nt * 8 + r;
                uint32_t b0 = Bs[swz(n, f0,     q)];
                uint32_t b1 = Bs[swz(n, f0 + 1, q)];
#pragma unroll
                for (int mt = 0; mt < MT; mt++) mma8(acc[mt][nt], a[mt], b0, b1);
            }
        }
        __syncthreads();
    }

    float* Of = TYPE ? (out + 2 * 4 * NL + (size_t)b * 4 * NL)
                     : (out + (size_t)b * 4 * NL);
    float* Os = out + 4 * 4 * NL + (size_t)b * 151 * NL;

#pragma unroll
    for (int mt = 0; mt < MT; mt++) {
        const int row = i0 + wy * (MT * 16) + mt * 16 + r;
#pragma unroll
        for (int nt = 0; nt < NTL; nt++) {
            const int cbase = wx * (NTL * 8) + nt * 8 + 2 * q;
#pragma unroll
            for (int hh = 0; hh < 2; hh++) {
                const int i = row + hh * 8;
#pragma unroll
                for (int dd = 0; dd < 2; dd++) {
                    const int cch = cbase + dd;
                    const float val = acc[mt][nt][hh * 2 + dd];
                    if (cch < 4) Of[(size_t)cch * NL + i] = val;
                    else if (TYPE && cch < 155) Os[(size_t)(cch - 4) * NL + i] = val;
                }
            }
        }
    }
}

#define GA1_SMEM (2 * (128 * 32 + 160 * 32) * 4)
#define GA0_SMEM (2 * (128 * 32 + 8 * 32) * 4)

// ---------------------------------------------------------------------------
extern "C" void kernel_launch(void* const* d_in, const int* in_sizes, int n_in,
                              void* d_out, int out_size) {
    const float* trg       = (const float*)d_in[0];
    const float* src       = (const float*)d_in[1];
    const float* ref       = (const float*)d_in[2];
    const float* src_feats = (const float*)d_in[3];
    const float* ref_feats = (const float*)d_in[4];
    const float* ref_sem   = (const float*)d_in[5];
    float* out = (float*)d_out;

    static bool attr_done = false;
    if (!attr_done) {
        cudaFuncSetAttribute(corr_kernel, cudaFuncAttributeMaxDynamicSharedMemorySize, CORR_SMEM);
        cudaFuncSetAttribute((const void*)gather_kernel<1, 160, 4, 2>,
                             cudaFuncAttributeMaxDynamicSharedMemorySize, GA1_SMEM);
        cudaFuncSetAttribute((const void*)gather_kernel<0, 8, 8, 1>,
                             cudaFuncAttributeMaxDynamicSharedMemorySize, GA0_SMEM);
        attr_done = true;
    }

    norm_kernel<<<dim3(NL / 32, NB, 3), 256>>>(trg, src, ref);
    vprep_kernel<<<dim3(NL / 256, 160, 4), 256>>>(src_feats, ref_feats, ref_sem);
    corr_kernel<<<dim3(NL / 128, NL / 128, 4), 256, CORR_SMEM>>>();
    softmax_kernel<<<dim3(NL, 4), 256>>>();
    gather_kernel<0, 8, 8, 1><<<dim3(NL / 128, 1, 2), 256, GA0_SMEM>>>(out);
    gather_kernel<1, 160, 4, 2><<<dim3(NL / 128, 1, 2), 256, GA1_SMEM>>>(out);
}

// round 4
// speedup vs baseline: 3.9745x; 1.1461x over previous
#include <cuda_runtime.h>
#include <cstdint>

#define NB 2
#define NC 256
#define NL 4096

// ---------------------------------------------------------------------------
// Scratch
// ---------------------------------------------------------------------------
__device__ float g_q [NB * NL * NC];        // normalized trg, [B][L][C] K-major, tf32
__device__ float g_ks[NB * NL * NC];
__device__ float g_kr[NB * NL * NC];
__device__ float g_v [4ull * 160 * NL];     // padded V banks per z, tf32
__device__ float g_p [4ull * NL * NL];      // exp(corr), tf32 (unnormalized softmax num)
__device__ float g_rsum[4 * NL];            // per-row sums of exp(corr)

// ---------------------------------------------------------------------------
// helpers
// ---------------------------------------------------------------------------
__device__ __forceinline__ uint32_t smem_u32(const void* p) {
    uint32_t a;
    asm("{ .reg .u64 t; cvta.to.shared.u64 t, %1; cvt.u32.u64 %0, t; }" : "=r"(a) : "l"(p));
    return a;
}
__device__ __forceinline__ float to_tf32(float x) {
    float r;
    asm("cvt.rna.tf32.f32 %0, %1;" : "=f"(r) : "f"(x));
    return r;
}

#define CPA16(dst, src) asm volatile("cp.async.cg.shared.global [%0], [%1], 16;" :: "r"(dst), "l"(src))
#define CPCOMMIT()      asm volatile("cp.async.commit_group;" ::: "memory")
#define CPWAIT(n)       asm volatile("cp.async.wait_group %0;" :: "n"(n) : "memory")

// smem tile index: rows of 32 floats, 4-float groups XOR-swizzled by row -> conflict-free
__device__ __forceinline__ int swz(int m, int f, int q) {
    return (m << 5) + (((f) ^ (m & 7)) << 2) + q;
}

__device__ __forceinline__ void mma8(float* d, const uint32_t* a, uint32_t b0, uint32_t b1) {
    asm volatile(
        "mma.sync.aligned.m16n8k8.row.col.f32.tf32.tf32.f32 "
        "{%0,%1,%2,%3}, {%4,%5,%6,%7}, {%8,%9}, {%0,%1,%2,%3};"
        : "+f"(d[0]), "+f"(d[1]), "+f"(d[2]), "+f"(d[3])
        : "r"(a[0]), "r"(a[1]), "r"(a[2]), "r"(a[3]), "r"(b0), "r"(b1));
}

// ---------------------------------------------------------------------------
// Kernel 0: zero the row-sum accumulators (graph-replay safe)
// ---------------------------------------------------------------------------
__global__ void __launch_bounds__(256) zero_kernel() {
    g_rsum[blockIdx.x * 256 + threadIdx.x] = 0.f;
}

// ---------------------------------------------------------------------------
// Kernel 1: normalize -> [B][L][C] K-major, tf32-rounded
// ---------------------------------------------------------------------------
__global__ void __launch_bounds__(256) norm_kernel(const float* __restrict__ trg,
                                                   const float* __restrict__ src,
                                                   const float* __restrict__ ref) {
    const int which = blockIdx.z;
    const float* x = (which == 0) ? trg : (which == 1) ? src : ref;
    float* y       = (which == 0) ? g_q : (which == 1) ? g_ks : g_kr;

    const int b = blockIdx.y;
    const int l0 = blockIdx.x * 32;
    const int t = threadIdx.x;
    const int l = t & 31;
    const int cg = t >> 5;

    __shared__ float buf[32][257];
    __shared__ float red[2][8][32];
    __shared__ float mi[2][32];

    const float* xb = x + (size_t)b * NC * NL + l0 + l;

    float s = 0.f, q = 0.f;
#pragma unroll 8
    for (int cc = 0; cc < 32; cc++) {
        const int c = cg * 32 + cc;
        float v = xb[(size_t)c * NL];
        buf[l][c] = v;
        s += v;
        q += v * v;
    }
    red[0][cg][l] = s;
    red[1][cg][l] = q;
    __syncthreads();

    if (t < 32) {
        float su = 0.f, ss = 0.f;
#pragma unroll
        for (int w = 0; w < 8; w++) { su += red[0][w][t]; ss += red[1][w][t]; }
        const float mean = su * (1.0f / NC);
        mi[0][t] = mean;
        mi[1][t] = rsqrtf(fmaxf(ss - su * mean, 1e-30f));
    }
    __syncthreads();

    const float mean = mi[0][l];
    const float inv = mi[1][l];
#pragma unroll 8
    for (int cc = 0; cc < 32; cc++) {
        const int c = cg * 32 + cc;
        buf[l][c] = to_tf32((buf[l][c] - mean) * inv);
    }
    __syncthreads();

    float* yb = y + (size_t)b * NL * NC + (size_t)l0 * NC;
#pragma unroll 8
    for (int r = 0; r < 32; r++) {
        yb[(size_t)r * NC + t] = buf[r][t];
    }
}

// ---------------------------------------------------------------------------
// Kernel 1b: build padded tf32 V banks. z<2: rows 0..7 (4 feats + 0s).
//            z>=2: rows 0..159 (4 feats, 151 sem, 5 zeros).
// ---------------------------------------------------------------------------
__global__ void __launch_bounds__(256) vprep_kernel(const float* __restrict__ sf,
                                                    const float* __restrict__ rf,
                                                    const float* __restrict__ rs) {
    const int z = blockIdx.z, b = z & 1, type = z >> 1;
    const int n = blockIdx.y;
    if (!type && n >= 8) return;
    const int l = blockIdx.x * 256 + threadIdx.x;
    float v = 0.f;
    if (n < 4) v = (type ? rf : sf)[(size_t)b * 4 * NL + (size_t)n * NL + l];
    else if (type && n < 155) v = rs[(size_t)b * 151 * NL + (size_t)(n - 4) * NL + l];
    g_v[(size_t)z * 160 * NL + (size_t)n * NL + l] = to_tf32(v);
}

// ---------------------------------------------------------------------------
// Kernel 2: corr = Q^T K via mma.sync tf32. CTA 128x128, BK=32, 2-stage
// cp.async. Epilogue: e = tf32(expf(s)) stored (cosine sims are in [-1,1] so
// exp needs no max subtraction); per-row partial sums atomicAdd'd to g_rsum.
// ---------------------------------------------------------------------------
#define CORR_SMEM 65536

__global__ void __launch_bounds__(256) corr_kernel() {
    extern __shared__ float dsm[];
    const int tid = threadIdx.x, lane = tid & 31, wid = tid >> 5;
    const int wy = wid & 3, wx = wid >> 2;
    const int z = blockIdx.z, b = z & 1, type = z >> 1;
    const int i0 = blockIdx.x * 128, j0 = blockIdx.y * 128;

    const float* __restrict__ A = g_q + (size_t)b * NL * NC;
    const float* __restrict__ B = (type ? g_kr : g_ks) + (size_t)b * NL * NC;
    float* __restrict__ Cm = g_p + (size_t)z * NL * NL;

    const uint32_t sbase = smem_u32(dsm);

    auto stage = [&](int st, int c0) {
        const uint32_t abase = sbase + (uint32_t)st * 8192u * 4u;
        const uint32_t bbase = abase + 4096u * 4u;
#pragma unroll
        for (int it = 0; it < 4; it++) {
            int idx = tid + it * 256, m = idx >> 3, f = idx & 7;
            CPA16(abase + swz(m, f, 0) * 4, A + (size_t)(i0 + m) * NC + c0 + f * 4);
        }
#pragma unroll
        for (int it = 0; it < 4; it++) {
            int idx = tid + it * 256, m = idx >> 3, f = idx & 7;
            CPA16(bbase + swz(m, f, 0) * 4, B + (size_t)(j0 + m) * NC + c0 + f * 4);
        }
    };

    float acc[2][8][4];
#pragma unroll
    for (int mt = 0; mt < 2; mt++)
#pragma unroll
        for (int nt = 0; nt < 8; nt++)
#pragma unroll
            for (int k = 0; k < 4; k++) acc[mt][nt][k] = 0.f;

    stage(0, 0); CPCOMMIT();

    const int q = lane & 3, r = lane >> 2;
    for (int c = 0; c < 8; c++) {
        if (c < 7) { stage((c + 1) & 1, (c + 1) * 32); CPCOMMIT(); CPWAIT(1); }
        else       { CPWAIT(0); }
        __syncthreads();
        const uint32_t* As = (const uint32_t*)(dsm + (c & 1) * 8192);
        const uint32_t* Bs = As + 4096;
#pragma unroll
        for (int ks = 0; ks < 4; ks++) {
            const int f0 = ks * 2;
            uint32_t a[2][4];
#pragma unroll
            for (int mt = 0; mt < 2; mt++) {
                const int m = wy * 32 + mt * 16 + r;
                a[mt][0] = As[swz(m,     f0,     q)];
                a[mt][1] = As[swz(m + 8, f0,     q)];
                a[mt][2] = As[swz(m,     f0 + 1, q)];
                a[mt][3] = As[swz(m + 8, f0 + 1, q)];
            }
#pragma unroll
            for (int nt = 0; nt < 8; nt++) {
                const int n = wx * 64 + nt * 8 + r;
                uint32_t b0 = Bs[swz(n, f0,     q)];
                uint32_t b1 = Bs[swz(n, f0 + 1, q)];
                mma8(acc[0][nt], a[0], b0, b1);
                mma8(acc[1][nt], a[1], b0, b1);
            }
        }
        __syncthreads();
    }

    // epilogue: exp + tf32 round + store + per-row partial sums
    float* rsum = g_rsum + z * NL;
#pragma unroll
    for (int mt = 0; mt < 2; mt++) {
        const int row = i0 + wy * 32 + mt * 16 + r;
        float rs0 = 0.f, rs1 = 0.f;
#pragma unroll
        for (int nt = 0; nt < 8; nt++) {
            const int col = j0 + wx * 64 + nt * 8 + 2 * q;
            const float e00 = to_tf32(__expf(acc[mt][nt][0]));
            const float e01 = to_tf32(__expf(acc[mt][nt][1]));
            const float e10 = to_tf32(__expf(acc[mt][nt][2]));
            const float e11 = to_tf32(__expf(acc[mt][nt][3]));
            *(float2*)&Cm[(size_t)row * NL + col]       = make_float2(e00, e01);
            *(float2*)&Cm[(size_t)(row + 8) * NL + col] = make_float2(e10, e11);
            rs0 += e00 + e01;
            rs1 += e10 + e11;
        }
        // reduce over the 4 lanes sharing this row (q = 0..3)
        rs0 += __shfl_xor_sync(0xffffffffu, rs0, 1);
        rs0 += __shfl_xor_sync(0xffffffffu, rs0, 2);
        rs1 += __shfl_xor_sync(0xffffffffu, rs1, 1);
        rs1 += __shfl_xor_sync(0xffffffffu, rs1, 2);
        if (q == 0) {
            atomicAdd(&rsum[row], rs0);
            atomicAdd(&rsum[row + 8], rs1);
        }
    }
}

// ---------------------------------------------------------------------------
// Kernel 4: gather out[c][i] = (sum_j e[i][j] V[c][j]) / rsum[i].
// ---------------------------------------------------------------------------
template <int TYPE, int NT, int WY, int WX>
__global__ void __launch_bounds__(256) gather_kernel(float* __restrict__ out) {
    constexpr int MT  = 128 / (WY * 16);
    constexpr int NTL = NT / (WX * 8);
    constexpr int ASZ = 128 * 32;
    constexpr int BSZ = NT * 32;

    extern __shared__ float dsm[];
    const int tid = threadIdx.x, lane = tid & 31, wid = tid >> 5;
    const int wy = wid % WY, wx = wid / WY;
    const int b = blockIdx.z, z = TYPE * 2 + b;
    const int i0 = blockIdx.x * 128;

    const float* __restrict__ P = g_p + (size_t)z * NL * NL;
    const float* __restrict__ V = g_v + (size_t)z * 160 * NL;

    const uint32_t sbase = smem_u32(dsm);

    auto stage = [&](int st, int j0) {
        const uint32_t abase = sbase + (uint32_t)st * (ASZ + BSZ) * 4u;
        const uint32_t bbase = abase + (uint32_t)ASZ * 4u;
#pragma unroll
        for (int it = 0; it < 4; it++) {
            int idx = tid + it * 256, m = idx >> 3, f = idx & 7;
            CPA16(abase + swz(m, f, 0) * 4, P + (size_t)(i0 + m) * NL + j0 + f * 4);
        }
        for (int idx = tid; idx < NT * 8; idx += 256) {
            int n = idx >> 3, f = idx & 7;
            CPA16(bbase + swz(n, f, 0) * 4, V + (size_t)n * NL + j0 + f * 4);
        }
    };

    float acc[MT][NTL][4];
#pragma unroll
    for (int mt = 0; mt < MT; mt++)
#pragma unroll
        for (int nt = 0; nt < NTL; nt++)
#pragma unroll
            for (int k = 0; k < 4; k++) acc[mt][nt][k] = 0.f;

    stage(0, 0); CPCOMMIT();

    const int q = lane & 3, r = lane >> 2;
    for (int c = 0; c < 128; c++) {
        if (c < 127) { stage((c + 1) & 1, (c + 1) * 32); CPCOMMIT(); CPWAIT(1); }
        else         { CPWAIT(0); }
        __syncthreads();
        const uint32_t* As = (const uint32_t*)(dsm + (c & 1) * (ASZ + BSZ));
        const uint32_t* Bs = As + ASZ;
#pragma unroll
        for (int ks = 0; ks < 4; ks++) {
            const int f0 = ks * 2;
            uint32_t a[MT][4];
#pragma unroll
            for (int mt = 0; mt < MT; mt++) {
                const int m = wy * (MT * 16) + mt * 16 + r;
                a[mt][0] = As[swz(m,     f0,     q)];
                a[mt][1] = As[swz(m + 8, f0,     q)];
                a[mt][2] = As[swz(m,     f0 + 1, q)];
                a[mt][3] = As[swz(m + 8, f0 + 1, q)];
            }
#pragma unroll
            for (int nt = 0; nt < NTL; nt++) {
                const int n = wx * (NTL * 8) + nt * 8 + r;
                uint32_t b0 = Bs[swz(n, f0,     q)];
                uint32_t b1 = Bs[swz(n, f0 + 1, q)];
#pragma unroll
                for (int mt = 0; mt < MT; mt++) mma8(acc[mt][nt], a[mt], b0, b1);
            }
        }
        __syncthreads();
    }

    float* Of = TYPE ? (out + 2 * 4 * NL + (size_t)b * 4 * NL)
                     : (out + (size_t)b * 4 * NL);
    float* Os = out + 4 * 4 * NL + (size_t)b * 151 * NL;
    const float* rsum = g_rsum + z * NL;

#pragma unroll
    for (int mt = 0; mt < MT; mt++) {
        const int row = i0 + wy * (MT * 16) + mt * 16 + r;
        const float inv0 = 1.0f / rsum[row];
        const float inv1 = 1.0f / rsum[row + 8];
#pragma unroll
        for (int nt = 0; nt < NTL; nt++) {
            const int cbase = wx * (NTL * 8) + nt * 8 + 2 * q;
#pragma unroll
            for (int hh = 0; hh < 2; hh++) {
                const int i = row + hh * 8;
                const float inv = hh ? inv1 : inv0;
#pragma unroll
                for (int dd = 0; dd < 2; dd++) {
                    const int cch = cbase + dd;
                    const float val = acc[mt][nt][hh * 2 + dd] * inv;
                    if (cch < 4) Of[(size_t)cch * NL + i] = val;
                    else if (TYPE && cch < 155) Os[(size_t)(cch - 4) * NL + i] = val;
                }
            }
        }
    }
}

#define GA1_SMEM (2 * (128 * 32 + 160 * 32) * 4)
#define GA0_SMEM (2 * (128 * 32 + 8 * 32) * 4)

// ---------------------------------------------------------------------------
extern "C" void kernel_launch(void* const* d_in, const int* in_sizes, int n_in,
                              void* d_out, int out_size) {
    const float* trg       = (const float*)d_in[0];
    const float* src       = (const float*)d_in[1];
    const float* ref       = (const float*)d_in[2];
    const float* src_feats = (const float*)d_in[3];
    const float* ref_feats = (const float*)d_in[4];
    const float* ref_sem   = (const float*)d_in[5];
    float* out = (float*)d_out;

    cudaFuncSetAttribute(corr_kernel, cudaFuncAttributeMaxDynamicSharedMemorySize, CORR_SMEM);
    cudaFuncSetAttribute((const void*)gather_kernel<1, 160, 4, 2>,
                         cudaFuncAttributeMaxDynamicSharedMemorySize, GA1_SMEM);
    cudaFuncSetAttribute((const void*)gather_kernel<0, 8, 8, 1>,
                         cudaFuncAttributeMaxDynamicSharedMemorySize, GA0_SMEM);

    zero_kernel<<<4 * NL / 256, 256>>>();
    norm_kernel<<<dim3(NL / 32, NB, 3), 256>>>(trg, src, ref);
    vprep_kernel<<<dim3(NL / 256, 160, 4), 256>>>(src_feats, ref_feats, ref_sem);
    corr_kernel<<<dim3(NL / 128, NL / 128, 4), 256, CORR_SMEM>>>();
    gather_kernel<0, 8, 8, 1><<<dim3(NL / 128, 1, 2), 256, GA0_SMEM>>>(out);
    gather_kernel<1, 160, 4, 2><<<dim3(NL / 128, 1, 2), 256, GA1_SMEM>>>(out);
}

// round 5
// speedup vs baseline: 4.6811x; 1.1778x over previous
#include <cuda_runtime.h>
#include <cstdint>

#define NB 2
#define NC 256
#define NL 4096

// ---------------------------------------------------------------------------
// Scratch
// ---------------------------------------------------------------------------
__device__ float g_q [NB * NL * NC];        // normalized trg, [B][L][C] K-major, tf32
__device__ float g_ks[NB * NL * NC];
__device__ float g_kr[NB * NL * NC];
__device__ float g_v [4ull * 160 * NL];     // padded V banks per z, tf32
__device__ float g_p [4ull * NL * NL];      // exp(corr), tf32 (unnormalized softmax num)
__device__ float g_rsum[4 * NL];            // per-row sums of exp(corr)

// ---------------------------------------------------------------------------
// helpers
// ---------------------------------------------------------------------------
__device__ __forceinline__ uint32_t smem_u32(const void* p) {
    uint32_t a;
    asm("{ .reg .u64 t; cvta.to.shared.u64 t, %1; cvt.u32.u64 %0, t; }" : "=r"(a) : "l"(p));
    return a;
}
__device__ __forceinline__ float to_tf32(float x) {
    float r;
    asm("cvt.rna.tf32.f32 %0, %1;" : "=f"(r) : "f"(x));
    return r;
}

#define CPA16(dst, src) asm volatile("cp.async.cg.shared.global [%0], [%1], 16;" :: "r"(dst), "l"(src))
#define CPCOMMIT()      asm volatile("cp.async.commit_group;" ::: "memory")
#define CPWAIT(n)       asm volatile("cp.async.wait_group %0;" :: "n"(n) : "memory")

#define LDSM_X4(R0, R1, R2, R3, A) \
    asm volatile("ldmatrix.sync.aligned.m8n8.x4.shared.b16 {%0,%1,%2,%3}, [%4];" \
                 : "=r"(R0), "=r"(R1), "=r"(R2), "=r"(R3) : "r"(A))
#define LDSM_X2(R0, R1, A) \
    asm volatile("ldmatrix.sync.aligned.m8n8.x2.shared.b16 {%0,%1}, [%2];" \
                 : "=r"(R0), "=r"(R1) : "r"(A))

// smem tile: rows of 32 floats, 4-float groups XOR-swizzled by row (conflict-free)
__device__ __forceinline__ int swz(int m, int f, int q) {
    return (m << 5) + (((f) ^ (m & 7)) << 2) + q;
}
// byte offset of the 16B group (m, f)
__device__ __forceinline__ uint32_t swzb(int m, int f) {
    return ((uint32_t)m << 7) + (uint32_t)(((f) ^ (m & 7)) << 4);
}

__device__ __forceinline__ void mma8(float* d, const uint32_t* a, uint32_t b0, uint32_t b1) {
    asm volatile(
        "mma.sync.aligned.m16n8k8.row.col.f32.tf32.tf32.f32 "
        "{%0,%1,%2,%3}, {%4,%5,%6,%7}, {%8,%9}, {%0,%1,%2,%3};"
        : "+f"(d[0]), "+f"(d[1]), "+f"(d[2]), "+f"(d[3])
        : "r"(a[0]), "r"(a[1]), "r"(a[2]), "r"(a[3]), "r"(b0), "r"(b1));
}

// ---------------------------------------------------------------------------
// Kernel 0: zero the row-sum accumulators (graph-replay safe)
// ---------------------------------------------------------------------------
__global__ void __launch_bounds__(256) zero_kernel() {
    g_rsum[blockIdx.x * 256 + threadIdx.x] = 0.f;
}

// ---------------------------------------------------------------------------
// Kernel 1: normalize -> [B][L][C] K-major, tf32-rounded
// ---------------------------------------------------------------------------
__global__ void __launch_bounds__(256) norm_kernel(const float* __restrict__ trg,
                                                   const float* __restrict__ src,
                                                   const float* __restrict__ ref) {
    const int which = blockIdx.z;
    const float* x = (which == 0) ? trg : (which == 1) ? src : ref;
    float* y       = (which == 0) ? g_q : (which == 1) ? g_ks : g_kr;

    const int b = blockIdx.y;
    const int l0 = blockIdx.x * 32;
    const int t = threadIdx.x;
    const int l = t & 31;
    const int cg = t >> 5;

    __shared__ float buf[32][257];
    __shared__ float red[2][8][32];
    __shared__ float mi[2][32];

    const float* xb = x + (size_t)b * NC * NL + l0 + l;

    float s = 0.f, q = 0.f;
#pragma unroll 8
    for (int cc = 0; cc < 32; cc++) {
        const int c = cg * 32 + cc;
        float v = xb[(size_t)c * NL];
        buf[l][c] = v;
        s += v;
        q += v * v;
    }
    red[0][cg][l] = s;
    red[1][cg][l] = q;
    __syncthreads();

    if (t < 32) {
        float su = 0.f, ss = 0.f;
#pragma unroll
        for (int w = 0; w < 8; w++) { su += red[0][w][t]; ss += red[1][w][t]; }
        const float mean = su * (1.0f / NC);
        mi[0][t] = mean;
        mi[1][t] = rsqrtf(fmaxf(ss - su * mean, 1e-30f));
    }
    __syncthreads();

    const float mean = mi[0][l];
    const float inv = mi[1][l];
#pragma unroll 8
    for (int cc = 0; cc < 32; cc++) {
        const int c = cg * 32 + cc;
        buf[l][c] = to_tf32((buf[l][c] - mean) * inv);
    }
    __syncthreads();

    float* yb = y + (size_t)b * NL * NC + (size_t)l0 * NC;
#pragma unroll 8
    for (int r = 0; r < 32; r++) {
        yb[(size_t)r * NC + t] = buf[r][t];
    }
}

// ---------------------------------------------------------------------------
// Kernel 1b: padded tf32 V banks. type0: rows 0..15 (4 feats + 12 zeros).
//            type1: rows 0..159 (4 feats, 151 sem, 5 zeros).
// ---------------------------------------------------------------------------
__global__ void __launch_bounds__(256) vprep_kernel(const float* __restrict__ sf,
                                                    const float* __restrict__ rf,
                                                    const float* __restrict__ rs) {
    const int z = blockIdx.z, b = z & 1, type = z >> 1;
    const int n = blockIdx.y;
    if (!type && n >= 16) return;
    const int l = blockIdx.x * 256 + threadIdx.x;
    float v = 0.f;
    if (n < 4) v = (type ? rf : sf)[(size_t)b * 4 * NL + (size_t)n * NL + l];
    else if (type && n < 155) v = rs[(size_t)b * 151 * NL + (size_t)(n - 4) * NL + l];
    g_v[(size_t)z * 160 * NL + (size_t)n * NL + l] = to_tf32(v);
}

// ---------------------------------------------------------------------------
// Kernel 2: corr = Q^T K via mma.sync tf32 + ldmatrix fragments.
// CTA 128x128, BK=32, 2-stage cp.async. Epilogue: exp + row-sum atomics.
// ---------------------------------------------------------------------------
#define CORR_SMEM 65536

__global__ void __launch_bounds__(256) corr_kernel() {
    extern __shared__ float dsm[];
    const int tid = threadIdx.x, lane = tid & 31, wid = tid >> 5;
    const int wy = wid & 3, wx = wid >> 2;
    const int z = blockIdx.z, b = z & 1, type = z >> 1;
    const int i0 = blockIdx.x * 128, j0 = blockIdx.y * 128;

    const float* __restrict__ A = g_q + (size_t)b * NL * NC;
    const float* __restrict__ B = (type ? g_kr : g_ks) + (size_t)b * NL * NC;
    float* __restrict__ Cm = g_p + (size_t)z * NL * NL;

    const uint32_t sbase = smem_u32(dsm);

    auto stage = [&](int st, int c0) {
        const uint32_t abase = sbase + (uint32_t)st * 32768u;
        const uint32_t bbase = abase + 16384u;
#pragma unroll
        for (int it = 0; it < 4; it++) {
            int idx = tid + it * 256, m = idx >> 3, f = idx & 7;
            CPA16(abase + swzb(m, f), A + (size_t)(i0 + m) * NC + c0 + f * 4);
        }
#pragma unroll
        for (int it = 0; it < 4; it++) {
            int idx = tid + it * 256, m = idx >> 3, f = idx & 7;
            CPA16(bbase + swzb(m, f), B + (size_t)(j0 + m) * NC + c0 + f * 4);
        }
    };

    // ldmatrix lane geometry
    const int a_fb = lane >> 4;             // col half
    uint32_t a_off[2]; int a_x[2];
#pragma unroll
    for (int mt = 0; mt < 2; mt++) {
        const int m = wy * 32 + mt * 16 + ((lane >> 3) & 1) * 8 + (lane & 7);
        a_off[mt] = (uint32_t)m << 7;
        a_x[mt] = m & 7;
    }
    const int b_fb = (lane >> 3) & 1;
    uint32_t b_off[4]; int b_x[4];
#pragma unroll
    for (int nt2 = 0; nt2 < 4; nt2++) {
        const int n = wx * 64 + nt2 * 16 + ((lane >> 4) & 1) * 8 + (lane & 7);
        b_off[nt2] = (uint32_t)n << 7;
        b_x[nt2] = n & 7;
    }

    float acc[2][8][4];
#pragma unroll
    for (int mt = 0; mt < 2; mt++)
#pragma unroll
        for (int nt = 0; nt < 8; nt++)
#pragma unroll
            for (int k = 0; k < 4; k++) acc[mt][nt][k] = 0.f;

    stage(0, 0); CPCOMMIT();

    for (int c = 0; c < 8; c++) {
        if (c < 7) { stage((c + 1) & 1, (c + 1) * 32); CPCOMMIT(); CPWAIT(1); }
        else       { CPWAIT(0); }
        __syncthreads();
        const uint32_t Ab = sbase + (uint32_t)(c & 1) * 32768u;
        const uint32_t Bb = Ab + 16384u;
#pragma unroll
        for (int ks = 0; ks < 4; ks++) {
            uint32_t a[2][4];
#pragma unroll
            for (int mt = 0; mt < 2; mt++) {
                const int f = 2 * ks + a_fb;
                LDSM_X4(a[mt][0], a[mt][1], a[mt][2], a[mt][3],
                        Ab + a_off[mt] + (uint32_t)((f ^ a_x[mt]) << 4));
            }
            uint32_t bb[4][4];
#pragma unroll
            for (int nt2 = 0; nt2 < 4; nt2++) {
                const int f = 2 * ks + b_fb;
                LDSM_X4(bb[nt2][0], bb[nt2][1], bb[nt2][2], bb[nt2][3],
                        Bb + b_off[nt2] + (uint32_t)((f ^ b_x[nt2]) << 4));
            }
#pragma unroll
            for (int nt2 = 0; nt2 < 4; nt2++) {
#pragma unroll
                for (int sub = 0; sub < 2; sub++) {
                    const int nt = nt2 * 2 + sub;
                    mma8(acc[0][nt], a[0], bb[nt2][sub * 2], bb[nt2][sub * 2 + 1]);
                    mma8(acc[1][nt], a[1], bb[nt2][sub * 2], bb[nt2][sub * 2 + 1]);
                }
            }
        }
        __syncthreads();
    }

    // epilogue: exp + tf32 round + store + per-row partial sums
    const int q = lane & 3, r = lane >> 2;
    float* rsum = g_rsum + z * NL;
#pragma unroll
    for (int mt = 0; mt < 2; mt++) {
        const int row = i0 + wy * 32 + mt * 16 + r;
        float rs0 = 0.f, rs1 = 0.f;
#pragma unroll
        for (int nt = 0; nt < 8; nt++) {
            const int col = j0 + wx * 64 + nt * 8 + 2 * q;
            const float e00 = to_tf32(__expf(acc[mt][nt][0]));
            const float e01 = to_tf32(__expf(acc[mt][nt][1]));
            const float e10 = to_tf32(__expf(acc[mt][nt][2]));
            const float e11 = to_tf32(__expf(acc[mt][nt][3]));
            *(float2*)&Cm[(size_t)row * NL + col]       = make_float2(e00, e01);
            *(float2*)&Cm[(size_t)(row + 8) * NL + col] = make_float2(e10, e11);
            rs0 += e00 + e01;
            rs1 += e10 + e11;
        }
        rs0 += __shfl_xor_sync(0xffffffffu, rs0, 1);
        rs0 += __shfl_xor_sync(0xffffffffu, rs0, 2);
        rs1 += __shfl_xor_sync(0xffffffffu, rs1, 1);
        rs1 += __shfl_xor_sync(0xffffffffu, rs1, 2);
        if (q == 0) {
            atomicAdd(&rsum[row], rs0);
            atomicAdd(&rsum[row + 8], rs1);
        }
    }
}

// ---------------------------------------------------------------------------
// Kernel 4: gather out[c][i] = (sum_j e[i][j] V[c][j]) / rsum[i].
// TYPE1: M=32, NT=160, WY=2, WX=4 (NTL=5). TYPE0: M=64, NT=16, WY=4, WX=2 (NTL=1).
// ---------------------------------------------------------------------------
template <int TYPE, int BM, int NT, int WY, int WX>
__global__ void __launch_bounds__(256) gather_kernel(float* __restrict__ out) {
    constexpr int NTL = NT / (WX * 8);
    constexpr int ASZ = BM * 32;
    constexpr int BSZ = NT * 32;

    extern __shared__ float dsm[];
    const int tid = threadIdx.x, lane = tid & 31, wid = tid >> 5;
    const int wy = wid % WY, wx = wid / WY;
    const int b = blockIdx.z, z = TYPE * 2 + b;
    const int i0 = blockIdx.x * BM;

    const float* __restrict__ P = g_p + (size_t)z * NL * NL;
    const float* __restrict__ V = g_v + (size_t)z * 160 * NL;

    const uint32_t sbase = smem_u32(dsm);

    auto stage = [&](int st, int j0) {
        const uint32_t abase = sbase + (uint32_t)st * (ASZ + BSZ) * 4u;
        const uint32_t bbase = abase + (uint32_t)ASZ * 4u;
#pragma unroll
        for (int it = 0; it < ASZ / 1024; it++) {
            int idx = tid + it * 256, m = idx >> 3, f = idx & 7;
            CPA16(abase + swzb(m, f), P + (size_t)(i0 + m) * NL + j0 + f * 4);
        }
        for (int idx = tid; idx < NT * 8; idx += 256) {
            int n = idx >> 3, f = idx & 7;
            CPA16(bbase + swzb(n, f), V + (size_t)n * NL + j0 + f * 4);
        }
    };

    // ldmatrix lane geometry
    const int a_fb = lane >> 4;
    const int m_l = wy * 16 + ((lane >> 3) & 1) * 8 + (lane & 7);
    const uint32_t a_off = (uint32_t)m_l << 7;
    const int a_x = m_l & 7;

    const int b_fb = (lane >> 3) & 1;
    constexpr int NP = NTL / 2;             // x4 pairs
    uint32_t b_off[NP ? NP : 1]; int b_x[NP ? NP : 1];
#pragma unroll
    for (int nt2 = 0; nt2 < NP; nt2++) {
        const int n = wx * (NTL * 8) + nt2 * 16 + ((lane >> 4) & 1) * 8 + (lane & 7);
        b_off[nt2] = (uint32_t)n << 7;
        b_x[nt2] = n & 7;
    }
    // odd tail tile (x2): lanes 0..15 give (row, fbit)
    const int n_t = wx * (NTL * 8) + (NTL & ~1) * 8 + (lane & 7);
    const uint32_t bt_off = (uint32_t)n_t << 7;
    const int bt_x = n_t & 7;

    float acc[NTL][4];
#pragma unroll
    for (int nt = 0; nt < NTL; nt++)
#pragma unroll
        for (int k = 0; k < 4; k++) acc[nt][k] = 0.f;

    stage(0, 0); CPCOMMIT();

    for (int c = 0; c < 128; c++) {
        if (c < 127) { stage((c + 1) & 1, (c + 1) * 32); CPCOMMIT(); CPWAIT(1); }
        else         { CPWAIT(0); }
        __syncthreads();
        const uint32_t Ab = sbase + (uint32_t)(c & 1) * (ASZ + BSZ) * 4u;
        const uint32_t Bb = Ab + (uint32_t)ASZ * 4u;
#pragma unroll
        for (int ks = 0; ks < 4; ks++) {
            uint32_t a[4];
            {
                const int f = 2 * ks + a_fb;
                LDSM_X4(a[0], a[1], a[2], a[3], Ab + a_off + (uint32_t)((f ^ a_x) << 4));
            }
#pragma unroll
            for (int nt2 = 0; nt2 < NP; nt2++) {
                uint32_t bb[4];
                const int f = 2 * ks + b_fb;
                LDSM_X4(bb[0], bb[1], bb[2], bb[3],
                        Bb + b_off[nt2] + (uint32_t)((f ^ b_x[nt2]) << 4));
                mma8(acc[nt2 * 2], a, bb[0], bb[1]);
                mma8(acc[nt2 * 2 + 1], a, bb[2], bb[3]);
            }
            if (NTL & 1) {
                uint32_t b0, b1;
                const int f = 2 * ks + b_fb;
                LDSM_X2(b0, b1, Bb + bt_off + (uint32_t)((f ^ bt_x) << 4));
                mma8(acc[NTL - 1], a, b0, b1);
            }
        }
        __syncthreads();
    }

    float* Of = TYPE ? (out + 2 * 4 * NL + (size_t)b * 4 * NL)
                     : (out + (size_t)b * 4 * NL);
    float* Os = out + 4 * 4 * NL + (size_t)b * 151 * NL;
    const float* rsum = g_rsum + z * NL;

    const int q = lane & 3, r = lane >> 2;
    const int row = i0 + wy * 16 + r;
    const float inv0 = 1.0f / rsum[row];
    const float inv1 = 1.0f / rsum[row + 8];
#pragma unroll
    for (int nt = 0; nt < NTL; nt++) {
        const int cbase = wx * (NTL * 8) + nt * 8 + 2 * q;
#pragma unroll
        for (int hh = 0; hh < 2; hh++) {
            const int i = row + hh * 8;
            const float inv = hh ? inv1 : inv0;
#pragma unroll
            for (int dd = 0; dd < 2; dd++) {
                const int cch = cbase + dd;
                const float val = acc[nt][hh * 2 + dd] * inv;
                if (cch < 4) Of[(size_t)cch * NL + i] = val;
                else if (TYPE && cch < 155) Os[(size_t)(cch - 4) * NL + i] = val;
            }
        }
    }
}

#define GA1_SMEM (2 * (32 * 32 + 160 * 32) * 4)
#define GA0_SMEM (2 * (64 * 32 + 16 * 32) * 4)

// ---------------------------------------------------------------------------
extern "C" void kernel_launch(void* const* d_in, const int* in_sizes, int n_in,
                              void* d_out, int out_size) {
    const float* trg       = (const float*)d_in[0];
    const float* src       = (const float*)d_in[1];
    const float* ref       = (const float*)d_in[2];
    const float* src_feats = (const float*)d_in[3];
    const float* ref_feats = (const float*)d_in[4];
    const float* ref_sem   = (const float*)d_in[5];
    float* out = (float*)d_out;

    cudaFuncSetAttribute(corr_kernel, cudaFuncAttributeMaxDynamicSharedMemorySize, CORR_SMEM);
    cudaFuncSetAttribute((const void*)gather_kernel<1, 32, 160, 2, 4>,
                         cudaFuncAttributeMaxDynamicSharedMemorySize, GA1_SMEM);
    cudaFuncSetAttribute((const void*)gather_kernel<0, 64, 16, 4, 2>,
                         cudaFuncAttributeMaxDynamicSharedMemorySize, GA0_SMEM);

    zero_kernel<<<4 * NL / 256, 256>>>();
    norm_kernel<<<dim3(NL / 32, NB, 3), 256>>>(trg, src, ref);
    vprep_kernel<<<dim3(NL / 256, 160, 4), 256>>>(src_feats, ref_feats, ref_sem);
    corr_kernel<<<dim3(NL / 128, NL / 128, 4), 256, CORR_SMEM>>>();
    gather_kernel<0, 64, 16, 4, 2><<<dim3(NL / 64, 1, 2), 256, GA0_SMEM>>>(out);
    gather_kernel<1, 32, 160, 2, 4><<<dim3(NL / 32, 1, 2), 256, GA1_SMEM>>>(out);
}

// round 6
// speedup vs baseline: 5.5909x; 1.1944x over previous
#include <cuda_runtime.h>
#include <cstdint>

#define NB 2
#define NC 256
#define NL 4096

// ---------------------------------------------------------------------------
// Scratch
// ---------------------------------------------------------------------------
__device__ float g_q [NB * NL * NC];        // normalized trg, [B][L][C] K-major, tf32
__device__ float g_ks[NB * NL * NC];
__device__ float g_kr[NB * NL * NC];
__device__ float g_v [4ull * 160 * NL];     // padded V banks per z, tf32
__device__ float g_p [4ull * NL * NL];      // exp(corr), tf32 (unnormalized softmax num)
__device__ float g_rsum[4 * NL];            // per-row sums of exp(corr)

// ---------------------------------------------------------------------------
// helpers
// ---------------------------------------------------------------------------
__device__ __forceinline__ uint32_t smem_u32(const void* p) {
    uint32_t a;
    asm("{ .reg .u64 t; cvta.to.shared.u64 t, %1; cvt.u32.u64 %0, t; }" : "=r"(a) : "l"(p));
    return a;
}
__device__ __forceinline__ float to_tf32(float x) {
    float r;
    asm("cvt.rna.tf32.f32 %0, %1;" : "=f"(r) : "f"(x));
    return r;
}

#define CPA16(dst, src) asm volatile("cp.async.cg.shared.global [%0], [%1], 16;" :: "r"(dst), "l"(src))
#define CPCOMMIT()      asm volatile("cp.async.commit_group;" ::: "memory")
#define CPWAIT(n)       asm volatile("cp.async.wait_group %0;" :: "n"(n) : "memory")

#define LDSM_X4(R0, R1, R2, R3, A) \
    asm volatile("ldmatrix.sync.aligned.m8n8.x4.shared.b16 {%0,%1,%2,%3}, [%4];" \
                 : "=r"(R0), "=r"(R1), "=r"(R2), "=r"(R3) : "r"(A))
#define LDSM_X2(R0, R1, A) \
    asm volatile("ldmatrix.sync.aligned.m8n8.x2.shared.b16 {%0,%1}, [%2];" \
                 : "=r"(R0), "=r"(R1) : "r"(A))

// byte offset of the 16B group (m, f) with row-XOR swizzle (conflict-free)
__device__ __forceinline__ uint32_t swzb(int m, int f) {
    return ((uint32_t)m << 7) + (uint32_t)(((f) ^ (m & 7)) << 4);
}

__device__ __forceinline__ void mma8(float* d, const uint32_t* a, uint32_t b0, uint32_t b1) {
    asm volatile(
        "mma.sync.aligned.m16n8k8.row.col.f32.tf32.tf32.f32 "
        "{%0,%1,%2,%3}, {%4,%5,%6,%7}, {%8,%9}, {%0,%1,%2,%3};"
        : "+f"(d[0]), "+f"(d[1]), "+f"(d[2]), "+f"(d[3])
        : "r"(a[0]), "r"(a[1]), "r"(a[2]), "r"(a[3]), "r"(b0), "r"(b1));
}

// ---------------------------------------------------------------------------
// Kernel 0: zero the row-sum accumulators (graph-replay safe)
// ---------------------------------------------------------------------------
__global__ void __launch_bounds__(256) zero_kernel() {
    g_rsum[blockIdx.x * 256 + threadIdx.x] = 0.f;
}

// ---------------------------------------------------------------------------
// Kernel 1: normalize -> [B][L][C] K-major, tf32-rounded
// ---------------------------------------------------------------------------
__global__ void __launch_bounds__(256) norm_kernel(const float* __restrict__ trg,
                                                   const float* __restrict__ src,
                                                   const float* __restrict__ ref) {
    const int which = blockIdx.z;
    const float* x = (which == 0) ? trg : (which == 1) ? src : ref;
    float* y       = (which == 0) ? g_q : (which == 1) ? g_ks : g_kr;

    const int b = blockIdx.y;
    const int l0 = blockIdx.x * 32;
    const int t = threadIdx.x;
    const int l = t & 31;
    const int cg = t >> 5;

    __shared__ float buf[32][257];
    __shared__ float red[2][8][32];
    __shared__ float mi[2][32];

    const float* xb = x + (size_t)b * NC * NL + l0 + l;

    float s = 0.f, q = 0.f;
#pragma unroll 8
    for (int cc = 0; cc < 32; cc++) {
        const int c = cg * 32 + cc;
        float v = xb[(size_t)c * NL];
        buf[l][c] = v;
        s += v;
        q += v * v;
    }
    red[0][cg][l] = s;
    red[1][cg][l] = q;
    __syncthreads();

    if (t < 32) {
        float su = 0.f, ss = 0.f;
#pragma unroll
        for (int w = 0; w < 8; w++) { su += red[0][w][t]; ss += red[1][w][t]; }
        const float mean = su * (1.0f / NC);
        mi[0][t] = mean;
        mi[1][t] = rsqrtf(fmaxf(ss - su * mean, 1e-30f));
    }
    __syncthreads();

    const float mean = mi[0][l];
    const float inv = mi[1][l];
#pragma unroll 8
    for (int cc = 0; cc < 32; cc++) {
        const int c = cg * 32 + cc;
        buf[l][c] = to_tf32((buf[l][c] - mean) * inv);
    }
    __syncthreads();

    float* yb = y + (size_t)b * NL * NC + (size_t)l0 * NC;
#pragma unroll 8
    for (int r = 0; r < 32; r++) {
        yb[(size_t)r * NC + t] = buf[r][t];
    }
}

// ---------------------------------------------------------------------------
// Kernel 1b: padded tf32 V banks. type0: rows 0..15 (4 feats + 12 zeros).
//            type1: rows 0..159 (4 feats, 151 sem, 5 zeros).
// ---------------------------------------------------------------------------
__global__ void __launch_bounds__(256) vprep_kernel(const float* __restrict__ sf,
                                                    const float* __restrict__ rf,
                                                    const float* __restrict__ rs) {
    const int z = blockIdx.z, b = z & 1, type = z >> 1;
    const int n = blockIdx.y;
    if (!type && n >= 16) return;
    const int l = blockIdx.x * 256 + threadIdx.x;
    float v = 0.f;
    if (n < 4) v = (type ? rf : sf)[(size_t)b * 4 * NL + (size_t)n * NL + l];
    else if (type && n < 155) v = rs[(size_t)b * 151 * NL + (size_t)(n - 4) * NL + l];
    g_v[(size_t)z * 160 * NL + (size_t)n * NL + l] = to_tf32(v);
}

// ---------------------------------------------------------------------------
// Kernel 2: corr = Q^T K via mma.sync tf32 + ldmatrix, 3-stage cp.async
// pipeline (one __syncthreads per BK-chunk). Epilogue: exp + row-sum atomics.
// ---------------------------------------------------------------------------
#define CORR_SMEM (3 * 32768)

__global__ void __launch_bounds__(256) corr_kernel() {
    extern __shared__ float dsm[];
    const int tid = threadIdx.x, lane = tid & 31, wid = tid >> 5;
    const int wy = wid & 3, wx = wid >> 2;
    const int z = blockIdx.z, b = z & 1, type = z >> 1;
    const int i0 = blockIdx.x * 128, j0 = blockIdx.y * 128;

    const float* __restrict__ A = g_q + (size_t)b * NL * NC;
    const float* __restrict__ B = (type ? g_kr : g_ks) + (size_t)b * NL * NC;
    float* __restrict__ Cm = g_p + (size_t)z * NL * NL;

    const uint32_t sbase = smem_u32(dsm);

    auto stage = [&](int buf, int c0) {
        const uint32_t abase = sbase + (uint32_t)buf * 32768u;
        const uint32_t bbase = abase + 16384u;
#pragma unroll
        for (int it = 0; it < 4; it++) {
            int idx = tid + it * 256, m = idx >> 3, f = idx & 7;
            CPA16(abase + swzb(m, f), A + (size_t)(i0 + m) * NC + c0 + f * 4);
        }
#pragma unroll
        for (int it = 0; it < 4; it++) {
            int idx = tid + it * 256, m = idx >> 3, f = idx & 7;
            CPA16(bbase + swzb(m, f), B + (size_t)(j0 + m) * NC + c0 + f * 4);
        }
    };

    // ldmatrix lane geometry
    const int a_fb = lane >> 4;
    uint32_t a_off[2]; int a_x[2];
#pragma unroll
    for (int mt = 0; mt < 2; mt++) {
        const int m = wy * 32 + mt * 16 + ((lane >> 3) & 1) * 8 + (lane & 7);
        a_off[mt] = (uint32_t)m << 7;
        a_x[mt] = m & 7;
    }
    const int b_fb = (lane >> 3) & 1;
    uint32_t b_off[4]; int b_x[4];
#pragma unroll
    for (int nt2 = 0; nt2 < 4; nt2++) {
        const int n = wx * 64 + nt2 * 16 + ((lane >> 4) & 1) * 8 + (lane & 7);
        b_off[nt2] = (uint32_t)n << 7;
        b_x[nt2] = n & 7;
    }

    float acc[2][8][4];
#pragma unroll
    for (int mt = 0; mt < 2; mt++)
#pragma unroll
        for (int nt = 0; nt < 8; nt++)
#pragma unroll
            for (int k = 0; k < 4; k++) acc[mt][nt][k] = 0.f;

    stage(0, 0); CPCOMMIT();
    stage(1, 32); CPCOMMIT();

    int buf = 0;
    for (int c = 0; c < 8; c++) {
        if (c < 7) { CPWAIT(1); } else { CPWAIT(0); }
        __syncthreads();
        const uint32_t Ab = sbase + (uint32_t)buf * 32768u;
        const uint32_t Bb = Ab + 16384u;
#pragma unroll
        for (int ks = 0; ks < 4; ks++) {
            uint32_t a[2][4];
#pragma unroll
            for (int mt = 0; mt < 2; mt++) {
                const int f = 2 * ks + a_fb;
                LDSM_X4(a[mt][0], a[mt][1], a[mt][2], a[mt][3],
                        Ab + a_off[mt] + (uint32_t)((f ^ a_x[mt]) << 4));
            }
            uint32_t bb[4][4];
#pragma unroll
            for (int nt2 = 0; nt2 < 4; nt2++) {
                const int f = 2 * ks + b_fb;
                LDSM_X4(bb[nt2][0], bb[nt2][1], bb[nt2][2], bb[nt2][3],
                        Bb + b_off[nt2] + (uint32_t)((f ^ b_x[nt2]) << 4));
            }
#pragma unroll
            for (int nt2 = 0; nt2 < 4; nt2++) {
#pragma unroll
                for (int sub = 0; sub < 2; sub++) {
                    const int nt = nt2 * 2 + sub;
                    mma8(acc[0][nt], a[0], bb[nt2][sub * 2], bb[nt2][sub * 2 + 1]);
                    mma8(acc[1][nt], a[1], bb[nt2][sub * 2], bb[nt2][sub * 2 + 1]);
                }
            }
        }
        if (c < 6) {
            int nb = buf + 2; if (nb >= 3) nb -= 3;
            stage(nb, (c + 2) * 32);
            CPCOMMIT();
        }
        if (++buf == 3) buf = 0;
    }

    // epilogue: exp + tf32 round + store + per-row partial sums
    const int q = lane & 3, r = lane >> 2;
    float* rsum = g_rsum + z * NL;
#pragma unroll
    for (int mt = 0; mt < 2; mt++) {
        const int row = i0 + wy * 32 + mt * 16 + r;
        float rs0 = 0.f, rs1 = 0.f;
#pragma unroll
        for (int nt = 0; nt < 8; nt++) {
            const int col = j0 + wx * 64 + nt * 8 + 2 * q;
            const float e00 = to_tf32(__expf(acc[mt][nt][0]));
            const float e01 = to_tf32(__expf(acc[mt][nt][1]));
            const float e10 = to_tf32(__expf(acc[mt][nt][2]));
            const float e11 = to_tf32(__expf(acc[mt][nt][3]));
            *(float2*)&Cm[(size_t)row * NL + col]       = make_float2(e00, e01);
            *(float2*)&Cm[(size_t)(row + 8) * NL + col] = make_float2(e10, e11);
            rs0 += e00 + e01;
            rs1 += e10 + e11;
        }
        rs0 += __shfl_xor_sync(0xffffffffu, rs0, 1);
        rs0 += __shfl_xor_sync(0xffffffffu, rs0, 2);
        rs1 += __shfl_xor_sync(0xffffffffu, rs1, 1);
        rs1 += __shfl_xor_sync(0xffffffffu, rs1, 2);
        if (q == 0) {
            atomicAdd(&rsum[row], rs0);
            atomicAdd(&rsum[row + 8], rs1);
        }
    }
}

// ---------------------------------------------------------------------------
// Gather body: out[c][i] = (sum_j e[i][j] V[c][j]) / rsum[i]. 3-stage pipeline.
// TYPE1: BM=32, NT=160, WY=2, WX=4 (NTL=5). TYPE0: BM=64, NT=16, WY=4, WX=2.
// ---------------------------------------------------------------------------
extern __shared__ float g_dsm[];

template <int TYPE, int BM, int NT, int WY, int WX>
__device__ __forceinline__ void gather_body(float* __restrict__ out, int b, int i0) {
    constexpr int NTL = NT / (WX * 8);
    constexpr int ASZ = BM * 32;
    constexpr int BSZ = NT * 32;
    constexpr uint32_t STG = (ASZ + BSZ) * 4;

    const int tid = threadIdx.x, lane = tid & 31, wid = tid >> 5;
    const int wy = wid % WY, wx = wid / WY;
    const int z = TYPE * 2 + b;

    const float* __restrict__ P = g_p + (size_t)z * NL * NL;
    const float* __restrict__ V = g_v + (size_t)z * 160 * NL;

    const uint32_t sbase = smem_u32(g_dsm);

    auto stage = [&](int st, int j0) {
        const uint32_t abase = sbase + (uint32_t)st * STG;
        const uint32_t bbase = abase + (uint32_t)(ASZ * 4);
#pragma unroll
        for (int it = 0; it < ASZ / 1024; it++) {
            int idx = tid + it * 256, m = idx >> 3, f = idx & 7;
            CPA16(abase + swzb(m, f), P + (size_t)(i0 + m) * NL + j0 + f * 4);
        }
        for (int idx = tid; idx < NT * 8; idx += 256) {
            int n = idx >> 3, f = idx & 7;
            CPA16(bbase + swzb(n, f), V + (size_t)n * NL + j0 + f * 4);
        }
    };

    // ldmatrix lane geometry
    const int a_fb = lane >> 4;
    const int m_l = wy * 16 + ((lane >> 3) & 1) * 8 + (lane & 7);
    const uint32_t a_off = (uint32_t)m_l << 7;
    const int a_x = m_l & 7;

    const int b_fb = (lane >> 3) & 1;
    constexpr int NP = NTL / 2;
    uint32_t b_off[NP ? NP : 1]; int b_x[NP ? NP : 1];
#pragma unroll
    for (int nt2 = 0; nt2 < NP; nt2++) {
        const int n = wx * (NTL * 8) + nt2 * 16 + ((lane >> 4) & 1) * 8 + (lane & 7);
        b_off[nt2] = (uint32_t)n << 7;
        b_x[nt2] = n & 7;
    }
    const int n_t = wx * (NTL * 8) + (NTL & ~1) * 8 + (lane & 7);
    const uint32_t bt_off = (uint32_t)n_t << 7;
    const int bt_x = n_t & 7;

    float acc[NTL][4];
#pragma unroll
    for (int nt = 0; nt < NTL; nt++)
#pragma unroll
        for (int k = 0; k < 4; k++) acc[nt][k] = 0.f;

    stage(0, 0); CPCOMMIT();
    stage(1, 32); CPCOMMIT();

    int buf = 0;
    for (int c = 0; c < 128; c++) {
        if (c < 127) { CPWAIT(1); } else { CPWAIT(0); }
        __syncthreads();
        const uint32_t Ab = sbase + (uint32_t)buf * STG;
        const uint32_t Bb = Ab + (uint32_t)(ASZ * 4);
#pragma unroll
        for (int ks = 0; ks < 4; ks++) {
            uint32_t a[4];
            {
                const int f = 2 * ks + a_fb;
                LDSM_X4(a[0], a[1], a[2], a[3], Ab + a_off + (uint32_t)((f ^ a_x) << 4));
            }
#pragma unroll
            for (int nt2 = 0; nt2 < NP; nt2++) {
                uint32_t bb[4];
                const int f = 2 * ks + b_fb;
                LDSM_X4(bb[0], bb[1], bb[2], bb[3],
                        Bb + b_off[nt2] + (uint32_t)((f ^ b_x[nt2]) << 4));
                mma8(acc[nt2 * 2], a, bb[0], bb[1]);
                mma8(acc[nt2 * 2 + 1], a, bb[2], bb[3]);
            }
            if (NTL & 1) {
                uint32_t b0, b1;
                const int f = 2 * ks + b_fb;
                LDSM_X2(b0, b1, Bb + bt_off + (uint32_t)((f ^ bt_x) << 4));
                mma8(acc[NTL - 1], a, b0, b1);
            }
        }
        if (c < 126) {
            int nb = buf + 2; if (nb >= 3) nb -= 3;
            stage(nb, (c + 2) * 32);
            CPCOMMIT();
        }
        if (++buf == 3) buf = 0;
    }

    float* Of = TYPE ? (out + 2 * 4 * NL + (size_t)b * 4 * NL)
                     : (out + (size_t)b * 4 * NL);
    float* Os = out + 4 * 4 * NL + (size_t)b * 151 * NL;
    const float* rsum = g_rsum + z * NL;

    const int q = lane & 3, r = lane >> 2;
    const int row = i0 + wy * 16 + r;
    const float inv0 = 1.0f / rsum[row];
    const float inv1 = 1.0f / rsum[row + 8];
#pragma unroll
    for (int nt = 0; nt < NTL; nt++) {
        const int cbase = wx * (NTL * 8) + nt * 8 + 2 * q;
#pragma unroll
        for (int hh = 0; hh < 2; hh++) {
            const int i = row + hh * 8;
            const float inv = hh ? inv1 : inv0;
#pragma unroll
            for (int dd = 0; dd < 2; dd++) {
                const int cch = cbase + dd;
                const float val = acc[nt][hh * 2 + dd] * inv;
                if (cch < 4) Of[(size_t)cch * NL + i] = val;
                else if (TYPE && cch < 155) Os[(size_t)(cch - 4) * NL + i] = val;
            }
        }
    }
}

// Merged gather: type1 CTAs first (longer), then type0. One launch -> overlap.
#define GA_SMEM (3 * (32 * 32 + 160 * 32) * 4)

__global__ void __launch_bounds__(256) gather_all_kernel(float* __restrict__ out) {
    const int idx = blockIdx.x;
    if (idx < 256) {
        gather_body<1, 32, 160, 2, 4>(out, idx >> 7, (idx & 127) * 32);
    } else {
        const int t = idx - 256;
        gather_body<0, 64, 16, 4, 2>(out, t >> 6, (t & 63) * 64);
    }
}

// ---------------------------------------------------------------------------
extern "C" void kernel_launch(void* const* d_in, const int* in_sizes, int n_in,
                              void* d_out, int out_size) {
    const float* trg       = (const float*)d_in[0];
    const float* src       = (const float*)d_in[1];
    const float* ref       = (const float*)d_in[2];
    const float* src_feats = (const float*)d_in[3];
    const float* ref_feats = (const float*)d_in[4];
    const float* ref_sem   = (const float*)d_in[5];
    float* out = (float*)d_out;

    cudaFuncSetAttribute(corr_kernel, cudaFuncAttributeMaxDynamicSharedMemorySize, CORR_SMEM);
    cudaFuncSetAttribute(gather_all_kernel, cudaFuncAttributeMaxDynamicSharedMemorySize, GA_SMEM);

    zero_kernel<<<4 * NL / 256, 256>>>();
    norm_kernel<<<dim3(NL / 32, NB, 3), 256>>>(trg, src, ref);
    vprep_kernel<<<dim3(NL / 256, 160, 4), 256>>>(src_feats, ref_feats, ref_sem);
    corr_kernel<<<dim3(NL / 128, NL / 128, 4), 256, CORR_SMEM>>>();
    gather_all_kernel<<<384, 256, GA_SMEM>>>(out);
}

// round 7
// speedup vs baseline: 5.9954x; 1.0723x over previous
#include <cuda_runtime.h>
#include <cstdint>

#define NB 2
#define NC 256
#define NL 4096

// ---------------------------------------------------------------------------
// Scratch
// ---------------------------------------------------------------------------
__device__ float g_q [NB * NL * NC];        // normalized trg, [B][L][C] K-major, tf32
__device__ float g_ks[NB * NL * NC];
__device__ float g_kr[NB * NL * NC];
__device__ float g_v [4ull * 160 * NL];     // padded V banks per z, tf32
__device__ float g_p [4ull * NL * NL];      // exp(corr), tf32 (unnormalized softmax num)
__device__ float g_rsum[4 * NL];            // per-row sums of exp(corr)

// ---------------------------------------------------------------------------
// helpers
// ---------------------------------------------------------------------------
__device__ __forceinline__ uint32_t smem_u32(const void* p) {
    uint32_t a;
    asm("{ .reg .u64 t; cvta.to.shared.u64 t, %1; cvt.u32.u64 %0, t; }" : "=r"(a) : "l"(p));
    return a;
}
__device__ __forceinline__ float to_tf32(float x) {
    float r;
    asm("cvt.rna.tf32.f32 %0, %1;" : "=f"(r) : "f"(x));
    return r;
}

#define CPA16(dst, src) asm volatile("cp.async.cg.shared.global [%0], [%1], 16;" :: "r"(dst), "l"(src))
#define CPCOMMIT()      asm volatile("cp.async.commit_group;" ::: "memory")
#define CPWAIT(n)       asm volatile("cp.async.wait_group %0;" :: "n"(n) : "memory")

#define LDSM_X4(R0, R1, R2, R3, A) \
    asm volatile("ldmatrix.sync.aligned.m8n8.x4.shared.b16 {%0,%1,%2,%3}, [%4];" \
                 : "=r"(R0), "=r"(R1), "=r"(R2), "=r"(R3) : "r"(A))

// byte offset of the 16B group (m, f) with row-XOR swizzle (conflict-free)
__device__ __forceinline__ uint32_t swzb(int m, int f) {
    return ((uint32_t)m << 7) + (uint32_t)(((f) ^ (m & 7)) << 4);
}

__device__ __forceinline__ void mma8(float* d, const uint32_t* a, uint32_t b0, uint32_t b1) {
    asm volatile(
        "mma.sync.aligned.m16n8k8.row.col.f32.tf32.tf32.f32 "
        "{%0,%1,%2,%3}, {%4,%5,%6,%7}, {%8,%9}, {%0,%1,%2,%3};"
        : "+f"(d[0]), "+f"(d[1]), "+f"(d[2]), "+f"(d[3])
        : "r"(a[0]), "r"(a[1]), "r"(a[2]), "r"(a[3]), "r"(b0), "r"(b1));
}

// ---------------------------------------------------------------------------
// Kernel 0: zero the row-sum accumulators (graph-replay safe)
// ---------------------------------------------------------------------------
__global__ void __launch_bounds__(256) zero_kernel() {
    g_rsum[blockIdx.x * 256 + threadIdx.x] = 0.f;
}

// ---------------------------------------------------------------------------
// Kernel 1: normalize -> [B][L][C] K-major, tf32-rounded
// ---------------------------------------------------------------------------
__global__ void __launch_bounds__(256) norm_kernel(const float* __restrict__ trg,
                                                   const float* __restrict__ src,
                                                   const float* __restrict__ ref) {
    const int which = blockIdx.z;
    const float* x = (which == 0) ? trg : (which == 1) ? src : ref;
    float* y       = (which == 0) ? g_q : (which == 1) ? g_ks : g_kr;

    const int b = blockIdx.y;
    const int l0 = blockIdx.x * 32;
    const int t = threadIdx.x;
    const int l = t & 31;
    const int cg = t >> 5;

    __shared__ float buf[32][257];
    __shared__ float red[2][8][32];
    __shared__ float mi[2][32];

    const float* xb = x + (size_t)b * NC * NL + l0 + l;

    float s = 0.f, q = 0.f;
#pragma unroll 8
    for (int cc = 0; cc < 32; cc++) {
        const int c = cg * 32 + cc;
        float v = xb[(size_t)c * NL];
        buf[l][c] = v;
        s += v;
        q += v * v;
    }
    red[0][cg][l] = s;
    red[1][cg][l] = q;
    __syncthreads();

    if (t < 32) {
        float su = 0.f, ss = 0.f;
#pragma unroll
        for (int w = 0; w < 8; w++) { su += red[0][w][t]; ss += red[1][w][t]; }
        const float mean = su * (1.0f / NC);
        mi[0][t] = mean;
        mi[1][t] = rsqrtf(fmaxf(ss - su * mean, 1e-30f));
    }
    __syncthreads();

    const float mean = mi[0][l];
    const float inv = mi[1][l];
#pragma unroll 8
    for (int cc = 0; cc < 32; cc++) {
        const int c = cg * 32 + cc;
        buf[l][c] = to_tf32((buf[l][c] - mean) * inv);
    }
    __syncthreads();

    float* yb = y + (size_t)b * NL * NC + (size_t)l0 * NC;
#pragma unroll 8
    for (int r = 0; r < 32; r++) {
        yb[(size_t)r * NC + t] = buf[r][t];
    }
}

// ---------------------------------------------------------------------------
// Kernel 1b: padded tf32 V banks. type0: rows 0..15 (4 feats + 12 zeros).
//            type1: rows 0..159 (4 feats, 151 sem, 5 zeros).
// ---------------------------------------------------------------------------
__global__ void __launch_bounds__(256) vprep_kernel(const float* __restrict__ sf,
                                                    const float* __restrict__ rf,
                                                    const float* __restrict__ rs) {
    const int z = blockIdx.z, b = z & 1, type = z >> 1;
    const int n = blockIdx.y;
    if (!type && n >= 16) return;
    const int l = blockIdx.x * 256 + threadIdx.x;
    float v = 0.f;
    if (n < 4) v = (type ? rf : sf)[(size_t)b * 4 * NL + (size_t)n * NL + l];
    else if (type && n < 155) v = rs[(size_t)b * 151 * NL + (size_t)(n - 4) * NL + l];
    g_v[(size_t)z * 160 * NL + (size_t)n * NL + l] = to_tf32(v);
}

// ---------------------------------------------------------------------------
// Kernel 2: corr = Q^T K, mma.sync tf32. 128-thread CTA, 2x2 warps of 64x64
// (CUTLASS-style double register blocking -> 8 MAC/smem-byte). 3-stage
// cp.async. Epilogue: exp + tf32 + store + row-sum atomics.
// ---------------------------------------------------------------------------
#define CORR_SMEM (3 * 32768)

__global__ void __launch_bounds__(128, 2) corr_kernel() {
    extern __shared__ float dsm[];
    const int tid = threadIdx.x, lane = tid & 31, wid = tid >> 5;
    const int wy = wid & 1, wx = wid >> 1;
    const int z = blockIdx.z, b = z & 1, type = z >> 1;
    const int i0 = blockIdx.x * 128, j0 = blockIdx.y * 128;

    const float* __restrict__ A = g_q + (size_t)b * NL * NC;
    const float* __restrict__ B = (type ? g_kr : g_ks) + (size_t)b * NL * NC;
    float* __restrict__ Cm = g_p + (size_t)z * NL * NL;

    const uint32_t sbase = smem_u32(dsm);

    auto stage = [&](int buf, int c0) {
        const uint32_t abase = sbase + (uint32_t)buf * 32768u;
        const uint32_t bbase = abase + 16384u;
#pragma unroll
        for (int it = 0; it < 8; it++) {
            int idx = tid + it * 128, m = idx >> 3, f = idx & 7;
            CPA16(abase + swzb(m, f), A + (size_t)(i0 + m) * NC + c0 + f * 4);
        }
#pragma unroll
        for (int it = 0; it < 8; it++) {
            int idx = tid + it * 128, m = idx >> 3, f = idx & 7;
            CPA16(bbase + swzb(m, f), B + (size_t)(j0 + m) * NC + c0 + f * 4);
        }
    };

    // ldmatrix lane geometry: warp rows wy*64 + mt*16, cols wx*64 + nt2*16
    const int a_fb = lane >> 4;
    uint32_t a_off[4]; int a_x[4];
#pragma unroll
    for (int mt = 0; mt < 4; mt++) {
        const int m = wy * 64 + mt * 16 + ((lane >> 3) & 1) * 8 + (lane & 7);
        a_off[mt] = (uint32_t)m << 7;
        a_x[mt] = m & 7;
    }
    const int b_fb = (lane >> 3) & 1;
    uint32_t b_off[4]; int b_x[4];
#pragma unroll
    for (int nt2 = 0; nt2 < 4; nt2++) {
        const int n = wx * 64 + nt2 * 16 + ((lane >> 4) & 1) * 8 + (lane & 7);
        b_off[nt2] = (uint32_t)n << 7;
        b_x[nt2] = n & 7;
    }

    float acc[4][8][4];
#pragma unroll
    for (int mt = 0; mt < 4; mt++)
#pragma unroll
        for (int nt = 0; nt < 8; nt++)
#pragma unroll
            for (int k = 0; k < 4; k++) acc[mt][nt][k] = 0.f;

    stage(0, 0); CPCOMMIT();
    stage(1, 32); CPCOMMIT();

    int buf = 0;
    for (int c = 0; c < 8; c++) {
        if (c < 7) { CPWAIT(1); } else { CPWAIT(0); }
        __syncthreads();
        const uint32_t Ab = sbase + (uint32_t)buf * 32768u;
        const uint32_t Bb = Ab + 16384u;
#pragma unroll
        for (int ks = 0; ks < 4; ks++) {
            uint32_t a[4][4];
#pragma unroll
            for (int mt = 0; mt < 4; mt++) {
                const int f = 2 * ks + a_fb;
                LDSM_X4(a[mt][0], a[mt][1], a[mt][2], a[mt][3],
                        Ab + a_off[mt] + (uint32_t)((f ^ a_x[mt]) << 4));
            }
            uint32_t bb[4][4];
#pragma unroll
            for (int nt2 = 0; nt2 < 4; nt2++) {
                const int f = 2 * ks + b_fb;
                LDSM_X4(bb[nt2][0], bb[nt2][1], bb[nt2][2], bb[nt2][3],
                        Bb + b_off[nt2] + (uint32_t)((f ^ b_x[nt2]) << 4));
            }
#pragma unroll
            for (int mt = 0; mt < 4; mt++)
#pragma unroll
                for (int nt2 = 0; nt2 < 4; nt2++) {
                    mma8(acc[mt][nt2 * 2],     a[mt], bb[nt2][0], bb[nt2][1]);
                    mma8(acc[mt][nt2 * 2 + 1], a[mt], bb[nt2][2], bb[nt2][3]);
                }
        }
        if (c < 6) {
            int nb = buf + 2; if (nb >= 3) nb -= 3;
            stage(nb, (c + 2) * 32);
            CPCOMMIT();
        }
        if (++buf == 3) buf = 0;
    }

    // epilogue: exp + tf32 round + store + per-row partial sums
    const int q = lane & 3, r = lane >> 2;
    float* rsum = g_rsum + z * NL;
#pragma unroll
    for (int mt = 0; mt < 4; mt++) {
        const int row = i0 + wy * 64 + mt * 16 + r;
        float rs0 = 0.f, rs1 = 0.f;
#pragma unroll
        for (int nt = 0; nt < 8; nt++) {
            const int col = j0 + wx * 64 + nt * 8 + 2 * q;
            const float e00 = to_tf32(__expf(acc[mt][nt][0]));
            const float e01 = to_tf32(__expf(acc[mt][nt][1]));
            const float e10 = to_tf32(__expf(acc[mt][nt][2]));
            const float e11 = to_tf32(__expf(acc[mt][nt][3]));
            *(float2*)&Cm[(size_t)row * NL + col]       = make_float2(e00, e01);
            *(float2*)&Cm[(size_t)(row + 8) * NL + col] = make_float2(e10, e11);
            rs0 += e00 + e01;
            rs1 += e10 + e11;
        }
        rs0 += __shfl_xor_sync(0xffffffffu, rs0, 1);
        rs0 += __shfl_xor_sync(0xffffffffu, rs0, 2);
        rs1 += __shfl_xor_sync(0xffffffffu, rs1, 1);
        rs1 += __shfl_xor_sync(0xffffffffu, rs1, 2);
        if (q == 0) {
            atomicAdd(&rsum[row], rs0);
            atomicAdd(&rsum[row + 8], rs1);
        }
    }
}

// ---------------------------------------------------------------------------
// Gather body (128-thread CTA): out[c][i] = (sum_j e[i][j] V[c][j]) / rsum[i].
// TYPE1: BM=64, NT=160, warps 2x2, warp 32x80 (NTL=10). TYPE0: BM=128, NT=16,
// warps 4x1, warp 32x16 (NTL=2). MT=2 rows-of-16 per warp in both.
// ---------------------------------------------------------------------------
extern __shared__ float g_dsm[];

template <int TYPE, int BM, int NT, int WY, int WX>
__device__ __forceinline__ void gather_body(float* __restrict__ out, int b, int i0) {
    constexpr int NTL = NT / (WX * 8);
    constexpr int NP = NTL / 2;
    constexpr int ASZ = BM * 32;
    constexpr int BSZ = NT * 32;
    constexpr uint32_t STG = (ASZ + BSZ) * 4;

    const int tid = threadIdx.x, lane = tid & 31, wid = tid >> 5;
    const int wy = wid % WY, wx = wid / WY;
    const int z = TYPE * 2 + b;

    const float* __restrict__ P = g_p + (size_t)z * NL * NL;
    const float* __restrict__ V = g_v + (size_t)z * 160 * NL;

    const uint32_t sbase = smem_u32(g_dsm);

    auto stage = [&](int st, int j0) {
        const uint32_t abase = sbase + (uint32_t)st * STG;
        const uint32_t bbase = abase + (uint32_t)(ASZ * 4);
#pragma unroll
        for (int it = 0; it < BM / 16; it++) {
            int idx = tid + it * 128, m = idx >> 3, f = idx & 7;
            CPA16(abase + swzb(m, f), P + (size_t)(i0 + m) * NL + j0 + f * 4);
        }
        for (int idx = tid; idx < NT * 8; idx += 128) {
            int n = idx >> 3, f = idx & 7;
            CPA16(bbase + swzb(n, f), V + (size_t)n * NL + j0 + f * 4);
        }
    };

    // ldmatrix lane geometry
    const int a_fb = lane >> 4;
    uint32_t a_off[2]; int a_x[2];
#pragma unroll
    for (int mt = 0; mt < 2; mt++) {
        const int m = wy * 32 + mt * 16 + ((lane >> 3) & 1) * 8 + (lane & 7);
        a_off[mt] = (uint32_t)m << 7;
        a_x[mt] = m & 7;
    }
    const int b_fb = (lane >> 3) & 1;
    uint32_t b_off[NP]; int b_x[NP];
#pragma unroll
    for (int nt2 = 0; nt2 < NP; nt2++) {
        const int n = wx * (NTL * 8) + nt2 * 16 + ((lane >> 4) & 1) * 8 + (lane & 7);
        b_off[nt2] = (uint32_t)n << 7;
        b_x[nt2] = n & 7;
    }

    float acc[2][NTL][4];
#pragma unroll
    for (int mt = 0; mt < 2; mt++)
#pragma unroll
        for (int nt = 0; nt < NTL; nt++)
#pragma unroll
            for (int k = 0; k < 4; k++) acc[mt][nt][k] = 0.f;

    stage(0, 0); CPCOMMIT();
    stage(1, 32); CPCOMMIT();

    int buf = 0;
    for (int c = 0; c < 128; c++) {
        if (c < 127) { CPWAIT(1); } else { CPWAIT(0); }
        __syncthreads();
        const uint32_t Ab = sbase + (uint32_t)buf * STG;
        const uint32_t Bb = Ab + (uint32_t)(ASZ * 4);
#pragma unroll
        for (int ks = 0; ks < 4; ks++) {
            uint32_t a[2][4];
#pragma unroll
            for (int mt = 0; mt < 2; mt++) {
                const int f = 2 * ks + a_fb;
                LDSM_X4(a[mt][0], a[mt][1], a[mt][2], a[mt][3],
                        Ab + a_off[mt] + (uint32_t)((f ^ a_x[mt]) << 4));
            }
#pragma unroll
            for (int nt2 = 0; nt2 < NP; nt2++) {
                uint32_t bb[4];
                const int f = 2 * ks + b_fb;
                LDSM_X4(bb[0], bb[1], bb[2], bb[3],
                        Bb + b_off[nt2] + (uint32_t)((f ^ b_x[nt2]) << 4));
#pragma unroll
                for (int mt = 0; mt < 2; mt++) {
                    mma8(acc[mt][nt2 * 2],     a[mt], bb[0], bb[1]);
                    mma8(acc[mt][nt2 * 2 + 1], a[mt], bb[2], bb[3]);
                }
            }
        }
        if (c < 126) {
            int nb = buf + 2; if (nb >= 3) nb -= 3;
            stage(nb, (c + 2) * 32);
            CPCOMMIT();
        }
        if (++buf == 3) buf = 0;
    }

    float* Of = TYPE ? (out + 2 * 4 * NL + (size_t)b * 4 * NL)
                     : (out + (size_t)b * 4 * NL);
    float* Os = out + 4 * 4 * NL + (size_t)b * 151 * NL;
    const float* rsum = g_rsum + z * NL;

    const int q = lane & 3, r = lane >> 2;
#pragma unroll
    for (int mt = 0; mt < 2; mt++) {
        const int row = i0 + wy * 32 + mt * 16 + r;
        const float inv0 = 1.0f / rsum[row];
        const float inv1 = 1.0f / rsum[row + 8];
#pragma unroll
        for (int nt = 0; nt < NTL; nt++) {
            const int cbase = wx * (NTL * 8) + nt * 8 + 2 * q;
#pragma unroll
            for (int hh = 0; hh < 2; hh++) {
                const int i = row + hh * 8;
                const float inv = hh ? inv1 : inv0;
#pragma unroll
                for (int dd = 0; dd < 2; dd++) {
                    const int cch = cbase + dd;
                    const float val = acc[mt][nt][hh * 2 + dd] * inv;
                    if (cch < 4) Of[(size_t)cch * NL + i] = val;
                    else if (TYPE && cch < 155) Os[(size_t)(cch - 4) * NL + i] = val;
                }
            }
        }
    }
}

// Merged gather: type1 CTAs first (128 of them), then type0 (64).
#define GA_SMEM (3 * (64 * 32 + 160 * 32) * 4)

__global__ void __launch_bounds__(128, 2) gather_all_kernel(float* __restrict__ out) {
    const int idx = blockIdx.x;
    if (idx < 128) {
        gather_body<1, 64, 160, 2, 2>(out, idx >> 6, (idx & 63) * 64);
    } else {
        const int t = idx - 128;
        gather_body<0, 128, 16, 4, 1>(out, t >> 5, (t & 31) * 128);
    }
}

// ---------------------------------------------------------------------------
extern "C" void kernel_launch(void* const* d_in, const int* in_sizes, int n_in,
                              void* d_out, int out_size) {
    const float* trg       = (const float*)d_in[0];
    const float* src       = (const float*)d_in[1];
    const float* ref       = (const float*)d_in[2];
    const float* src_feats = (const float*)d_in[3];
    const float* ref_feats = (const float*)d_in[4];
    const float* ref_sem   = (const float*)d_in[5];
    float* out = (float*)d_out;

    cudaFuncSetAttribute(corr_kernel, cudaFuncAttributeMaxDynamicSharedMemorySize, CORR_SMEM);
    cudaFuncSetAttribute(gather_all_kernel, cudaFuncAttributeMaxDynamicSharedMemorySize, GA_SMEM);

    zero_kernel<<<4 * NL / 256, 256>>>();
    norm_kernel<<<dim3(NL / 32, NB, 3), 256>>>(trg, src, ref);
    vprep_kernel<<<dim3(NL / 256, 160, 4), 256>>>(src_feats, ref_feats, ref_sem);
    corr_kernel<<<dim3(NL / 128, NL / 128, 4), 128, CORR_SMEM>>>();
    gather_all_kernel<<<192, 128, GA_SMEM>>>(out);
}

// round 8
// speedup vs baseline: 6.6267x; 1.1053x over previous
#include <cuda_runtime.h>
#include <cuda_fp16.h>
#include <cstdint>

#define NB 2
#define NC 256
#define NL 4096

// ---------------------------------------------------------------------------
// Scratch (all GEMM operands fp16; accumulation fp32)
// ---------------------------------------------------------------------------
__device__ __half g_q [NB * NL * NC];       // normalized trg, [B][L][C] K-major
__device__ __half g_ks[NB * NL * NC];
__device__ __half g_kr[NB * NL * NC];
__device__ __half g_v [4ull * 160 * NL];    // padded V banks per z
__device__ __half g_p [4ull * NL * NL];     // exp(corr) (unnormalized softmax num)
__device__ float  g_rsum[4 * NL];           // per-row sums of exp(corr)

// ---------------------------------------------------------------------------
// helpers
// ---------------------------------------------------------------------------
__device__ __forceinline__ uint32_t smem_u32(const void* p) {
    uint32_t a;
    asm("{ .reg .u64 t; cvta.to.shared.u64 t, %1; cvt.u32.u64 %0, t; }" : "=r"(a) : "l"(p));
    return a;
}

#define CPA16(dst, src) asm volatile("cp.async.cg.shared.global [%0], [%1], 16;" :: "r"(dst), "l"(src))
#define CPCOMMIT()      asm volatile("cp.async.commit_group;" ::: "memory")
#define CPWAIT(n)       asm volatile("cp.async.wait_group %0;" :: "n"(n) : "memory")

#define LDSM_X4(R0, R1, R2, R3, A) \
    asm volatile("ldmatrix.sync.aligned.m8n8.x4.shared.b16 {%0,%1,%2,%3}, [%4];" \
                 : "=r"(R0), "=r"(R1), "=r"(R2), "=r"(R3) : "r"(A))

// byte offset of the 16B group (m, f) in a 128B-row tile, row-XOR swizzled
__device__ __forceinline__ uint32_t swzb(int m, int f) {
    return ((uint32_t)m << 7) + (uint32_t)(((f) ^ (m & 7)) << 4);
}

// fp16 MMA, fp32 accumulate: m16n8k16
__device__ __forceinline__ void mma16(float* d, const uint32_t* a, uint32_t b0, uint32_t b1) {
    asm volatile(
        "mma.sync.aligned.m16n8k16.row.col.f32.f16.f16.f32 "
        "{%0,%1,%2,%3}, {%4,%5,%6,%7}, {%8,%9}, {%0,%1,%2,%3};"
        : "+f"(d[0]), "+f"(d[1]), "+f"(d[2]), "+f"(d[3])
        : "r"(a[0]), "r"(a[1]), "r"(a[2]), "r"(a[3]), "r"(b0), "r"(b1));
}

// ---------------------------------------------------------------------------
// Kernel 0: zero the row-sum accumulators (graph-replay safe)
// ---------------------------------------------------------------------------
__global__ void __launch_bounds__(256) zero_kernel() {
    g_rsum[blockIdx.x * 256 + threadIdx.x] = 0.f;
}

// ---------------------------------------------------------------------------
// Kernel 1: normalize -> [B][L][C] K-major, fp16
// ---------------------------------------------------------------------------
__global__ void __launch_bounds__(256) norm_kernel(const float* __restrict__ trg,
                                                   const float* __restrict__ src,
                                                   const float* __restrict__ ref) {
    const int which = blockIdx.z;
    const float* x = (which == 0) ? trg : (which == 1) ? src : ref;
    __half* y      = (which == 0) ? g_q : (which == 1) ? g_ks : g_kr;

    const int b = blockIdx.y;
    const int l0 = blockIdx.x * 32;
    const int t = threadIdx.x;
    const int l = t & 31;
    const int cg = t >> 5;

    __shared__ float buf[32][257];
    __shared__ float red[2][8][32];
    __shared__ float mi[2][32];

    const float* xb = x + (size_t)b * NC * NL + l0 + l;

    float s = 0.f, q = 0.f;
#pragma unroll 8
    for (int cc = 0; cc < 32; cc++) {
        const int c = cg * 32 + cc;
        float v = xb[(size_t)c * NL];
        buf[l][c] = v;
        s += v;
        q += v * v;
    }
    red[0][cg][l] = s;
    red[1][cg][l] = q;
    __syncthreads();

    if (t < 32) {
        float su = 0.f, ss = 0.f;
#pragma unroll
        for (int w = 0; w < 8; w++) { su += red[0][w][t]; ss += red[1][w][t]; }
        const float mean = su * (1.0f / NC);
        mi[0][t] = mean;
        mi[1][t] = rsqrtf(fmaxf(ss - su * mean, 1e-30f));
    }
    __syncthreads();

    const float mean = mi[0][l];
    const float inv = mi[1][l];
#pragma unroll 8
    for (int cc = 0; cc < 32; cc++) {
        const int c = cg * 32 + cc;
        buf[l][c] = (buf[l][c] - mean) * inv;
    }
    __syncthreads();

    __half* yb = y + (size_t)b * NL * NC + (size_t)l0 * NC;
#pragma unroll 8
    for (int r = 0; r < 32; r++) {
        yb[(size_t)r * NC + t] = __float2half_rn(buf[r][t]);
    }
}

// ---------------------------------------------------------------------------
// Kernel 1b: padded fp16 V banks. type0: rows 0..15 (4 feats + 12 zeros).
//            type1: rows 0..159 (4 feats, 151 sem, 5 zeros).
// ---------------------------------------------------------------------------
__global__ void __launch_bounds__(256) vprep_kernel(const float* __restrict__ sf,
                                                    const float* __restrict__ rf,
                                                    const float* __restrict__ rs) {
    const int z = blockIdx.z, b = z & 1, type = z >> 1;
    const int n = blockIdx.y;
    if (!type && n >= 16) return;
    const int l = blockIdx.x * 256 + threadIdx.x;
    float v = 0.f;
    if (n < 4) v = (type ? rf : sf)[(size_t)b * 4 * NL + (size_t)n * NL + l];
    else if (type && n < 155) v = rs[(size_t)b * 151 * NL + (size_t)(n - 4) * NL + l];
    g_v[(size_t)z * 160 * NL + (size_t)n * NL + l] = __float2half_rn(v);
}

// ---------------------------------------------------------------------------
// Kernel 2: corr = Q^T K, fp16 mma m16n8k16. 128-thread CTA, 2x2 warps of
// 64x64. BK=64 (128B rows -> same swizzle/ldmatrix geometry as tf32 BK=32).
// K=256 in 4 chunks, 3-stage cp.async. Epilogue: exp -> fp16 store + row sums.
// ---------------------------------------------------------------------------
#define CORR_SMEM (3 * 32768)

__global__ void __launch_bounds__(128, 2) corr_kernel() {
    extern __shared__ char dsm[];
    const int tid = threadIdx.x, lane = tid & 31, wid = tid >> 5;
    const int wy = wid & 1, wx = wid >> 1;
    const int z = blockIdx.z, b = z & 1, type = z >> 1;
    const int i0 = blockIdx.x * 128, j0 = blockIdx.y * 128;

    const __half* __restrict__ A = g_q + (size_t)b * NL * NC;
    const __half* __restrict__ B = (type ? g_kr : g_ks) + (size_t)b * NL * NC;
    __half* __restrict__ Cm = g_p + (size_t)z * NL * NL;

    const uint32_t sbase = smem_u32(dsm);

    auto stage = [&](int buf, int c0) {
        const uint32_t abase = sbase + (uint32_t)buf * 32768u;
        const uint32_t bbase = abase + 16384u;
#pragma unroll
        for (int it = 0; it < 8; it++) {
            int idx = tid + it * 128, m = idx >> 3, f = idx & 7;
            CPA16(abase + swzb(m, f), A + (size_t)(i0 + m) * NC + c0 + f * 8);
        }
#pragma unroll
        for (int it = 0; it < 8; it++) {
            int idx = tid + it * 128, m = idx >> 3, f = idx & 7;
            CPA16(bbase + swzb(m, f), B + (size_t)(j0 + m) * NC + c0 + f * 8);
        }
    };

    // ldmatrix lane geometry (identical to tf32 version; 16B group = 8 fp16)
    const int a_fb = lane >> 4;
    uint32_t a_off[4]; int a_x[4];
#pragma unroll
    for (int mt = 0; mt < 4; mt++) {
        const int m = wy * 64 + mt * 16 + ((lane >> 3) & 1) * 8 + (lane & 7);
        a_off[mt] = (uint32_t)m << 7;
        a_x[mt] = m & 7;
    }
    const int b_fb = (lane >> 3) & 1;
    uint32_t b_off[4]; int b_x[4];
#pragma unroll
    for (int nt2 = 0; nt2 < 4; nt2++) {
        const int n = wx * 64 + nt2 * 16 + ((lane >> 4) & 1) * 8 + (lane & 7);
        b_off[nt2] = (uint32_t)n << 7;
        b_x[nt2] = n & 7;
    }

    float acc[4][8][4];
#pragma unroll
    for (int mt = 0; mt < 4; mt++)
#pragma unroll
        for (int nt = 0; nt < 8; nt++)
#pragma unroll
            for (int k = 0; k < 4; k++) acc[mt][nt][k] = 0.f;

    stage(0, 0); CPCOMMIT();
    stage(1, 64); CPCOMMIT();

    int buf = 0;
    for (int c = 0; c < 4; c++) {
        if (c < 3) { CPWAIT(1); } else { CPWAIT(0); }
        __syncthreads();
        const uint32_t Ab = sbase + (uint32_t)buf * 32768u;
        const uint32_t Bb = Ab + 16384u;
#pragma unroll
        for (int ks = 0; ks < 4; ks++) {   // k16 per step: 2 groups of 16B
            uint32_t a[4][4];
#pragma unroll
            for (int mt = 0; mt < 4; mt++) {
                const int f = 2 * ks + a_fb;
                LDSM_X4(a[mt][0], a[mt][1], a[mt][2], a[mt][3],
                        Ab + a_off[mt] + (uint32_t)((f ^ a_x[mt]) << 4));
            }
            uint32_t bb[4][4];
#pragma unroll
            for (int nt2 = 0; nt2 < 4; nt2++) {
                const int f = 2 * ks + b_fb;
                LDSM_X4(bb[nt2][0], bb[nt2][1], bb[nt2][2], bb[nt2][3],
                        Bb + b_off[nt2] + (uint32_t)((f ^ b_x[nt2]) << 4));
            }
#pragma unroll
            for (int mt = 0; mt < 4; mt++)
#pragma unroll
                for (int nt2 = 0; nt2 < 4; nt2++) {
                    mma16(acc[mt][nt2 * 2],     a[mt], bb[nt2][0], bb[nt2][1]);
                    mma16(acc[mt][nt2 * 2 + 1], a[mt], bb[nt2][2], bb[nt2][3]);
                }
        }
        if (c < 2) {
            int nb = buf + 2; if (nb >= 3) nb -= 3;
            stage(nb, (c + 2) * 64);
            CPCOMMIT();
        }
        if (++buf == 3) buf = 0;
    }

    // epilogue: exp -> fp16 round -> store + per-row partial sums (of rounded)
    const int q = lane & 3, r = lane >> 2;
    float* rsum = g_rsum + z * NL;
#pragma unroll
    for (int mt = 0; mt < 4; mt++) {
        const int row = i0 + wy * 64 + mt * 16 + r;
        float rs0 = 0.f, rs1 = 0.f;
#pragma unroll
        for (int nt = 0; nt < 8; nt++) {
            const int col = j0 + wx * 64 + nt * 8 + 2 * q;
            const __half h00 = __float2half_rn(__expf(acc[mt][nt][0]));
            const __half h01 = __float2half_rn(__expf(acc[mt][nt][1]));
            const __half h10 = __float2half_rn(__expf(acc[mt][nt][2]));
            const __half h11 = __float2half_rn(__expf(acc[mt][nt][3]));
            *(__half2*)&Cm[(size_t)row * NL + col]       = __halves2half2(h00, h01);
            *(__half2*)&Cm[(size_t)(row + 8) * NL + col] = __halves2half2(h10, h11);
            rs0 += __half2float(h00) + __half2float(h01);
            rs1 += __half2float(h10) + __half2float(h11);
        }
        rs0 += __shfl_xor_sync(0xffffffffu, rs0, 1);
        rs0 += __shfl_xor_sync(0xffffffffu, rs0, 2);
        rs1 += __shfl_xor_sync(0xffffffffu, rs1, 1);
        rs1 += __shfl_xor_sync(0xffffffffu, rs1, 2);
        if (q == 0) {
            atomicAdd(&rsum[row], rs0);
            atomicAdd(&rsum[row + 8], rs1);
        }
    }
}

// ---------------------------------------------------------------------------
// Gather body (128-thread CTA): out[c][i] = (sum_j e[i][j] V[c][j]) / rsum[i].
// BK=64 fp16, K=4096 -> 64 chunks. TYPE1: BM=64, NT=160, warps 2x2 (NTL=10).
// TYPE0: BM=128, NT=16, warps 4x1 (NTL=2).
// ---------------------------------------------------------------------------
extern __shared__ char g_dsm[];

template <int TYPE, int BM, int NT, int WY, int WX>
__device__ __forceinline__ void gather_body(float* __restrict__ out, int b, int i0) {
    constexpr int NTL = NT / (WX * 8);
    constexpr int NP = NTL / 2;
    constexpr uint32_t ABYTES = BM * 128;
    constexpr uint32_t STG = (BM + NT) * 128;

    const int tid = threadIdx.x, lane = tid & 31, wid = tid >> 5;
    const int wy = wid % WY, wx = wid / WY;
    const int z = TYPE * 2 + b;

    const __half* __restrict__ P = g_p + (size_t)z * NL * NL;
    const __half* __restrict__ V = g_v + (size_t)z * 160 * NL;

    const uint32_t sbase = smem_u32(g_dsm);

    auto stage = [&](int st, int j0) {
        const uint32_t abase = sbase + (uint32_t)st * STG;
        const uint32_t bbase = abase + ABYTES;
#pragma unroll
        for (int it = 0; it < BM * 8 / 128; it++) {
            int idx = tid + it * 128, m = idx >> 3, f = idx & 7;
            CPA16(abase + swzb(m, f), P + (size_t)(i0 + m) * NL + j0 + f * 8);
        }
        for (int idx = tid; idx < NT * 8; idx += 128) {
            int n = idx >> 3, f = idx & 7;
            CPA16(bbase + swzb(n, f), V + (size_t)n * NL + j0 + f * 8);
        }
    };

    const int a_fb = lane >> 4;
    uint32_t a_off[2]; int a_x[2];
#pragma unroll
    for (int mt = 0; mt < 2; mt++) {
        const int m = wy * 32 + mt * 16 + ((lane >> 3) & 1) * 8 + (lane & 7);
        a_off[mt] = (uint32_t)m << 7;
        a_x[mt] = m & 7;
    }
    const int b_fb = (lane >> 3) & 1;
    uint32_t b_off[NP]; int b_x[NP];
#pragma unroll
    for (int nt2 = 0; nt2 < NP; nt2++) {
        const int n = wx * (NTL * 8) + nt2 * 16 + ((lane >> 4) & 1) * 8 + (lane & 7);
        b_off[nt2] = (uint32_t)n << 7;
        b_x[nt2] = n & 7;
    }

    float acc[2][NTL][4];
#pragma unroll
    for (int mt = 0; mt < 2; mt++)
#pragma unroll
        for (int nt = 0; nt < NTL; nt++)
#pragma unroll
            for (int k = 0; k < 4; k++) acc[mt][nt][k] = 0.f;

    stage(0, 0); CPCOMMIT();
    stage(1, 64); CPCOMMIT();

    int buf = 0;
    for (int c = 0; c < 64; c++) {
        if (c < 63) { CPWAIT(1); } else { CPWAIT(0); }
        __syncthreads();
        const uint32_t Ab = sbase + (uint32_t)buf * STG;
        const uint32_t Bb = Ab + ABYTES;
#pragma unroll
        for (int ks = 0; ks < 4; ks++) {
            uint32_t a[2][4];
#pragma unroll
            for (int mt = 0; mt < 2; mt++) {
                const int f = 2 * ks + a_fb;
                LDSM_X4(a[mt][0], a[mt][1], a[mt][2], a[mt][3],
                        Ab + a_off[mt] + (uint32_t)((f ^ a_x[mt]) << 4));
            }
#pragma unroll
            for (int nt2 = 0; nt2 < NP; nt2++) {
                uint32_t bb[4];
                const int f = 2 * ks + b_fb;
                LDSM_X4(bb[0], bb[1], bb[2], bb[3],
                        Bb + b_off[nt2] + (uint32_t)((f ^ b_x[nt2]) << 4));
#pragma unroll
                for (int mt = 0; mt < 2; mt++) {
                    mma16(acc[mt][nt2 * 2],     a[mt], bb[0], bb[1]);
                    mma16(acc[mt][nt2 * 2 + 1], a[mt], bb[2], bb[3]);
                }
            }
        }
        if (c < 62) {
            int nb = buf + 2; if (nb >= 3) nb -= 3;
            stage(nb, (c + 2) * 64);
            CPCOMMIT();
        }
        if (++buf == 3) buf = 0;
    }

    float* Of = TYPE ? (out + 2 * 4 * NL + (size_t)b * 4 * NL)
                     : (out + (size_t)b * 4 * NL);
    float* Os = out + 4 * 4 * NL + (size_t)b * 151 * NL;
    const float* rsum = g_rsum + z * NL;

    const int q = lane & 3, r = lane >> 2;
#pragma unroll
    for (int mt = 0; mt < 2; mt++) {
        const int row = i0 + wy * 32 + mt * 16 + r;
        const float inv0 = 1.0f / rsum[row];
        const float inv1 = 1.0f / rsum[row + 8];
#pragma unroll
        for (int nt = 0; nt < NTL; nt++) {
            const int cbase = wx * (NTL * 8) + nt * 8 + 2 * q;
#pragma unroll
            for (int hh = 0; hh < 2; hh++) {
                const int i = row + hh * 8;
                const float inv = hh ? inv1 : inv0;
#pragma unroll
                for (int dd = 0; dd < 2; dd++) {
                    const int cch = cbase + dd;
                    const float val = acc[mt][nt][hh * 2 + dd] * inv;
                    if (cch < 4) Of[(size_t)cch * NL + i] = val;
                    else if (TYPE && cch < 155) Os[(size_t)(cch - 4) * NL + i] = val;
                }
            }
        }
    }
}

// Merged gather: type1 CTAs first (128), then type0 (64).
#define GA_SMEM (3 * (64 + 160) * 128)

__global__ void __launch_bounds__(128, 2) gather_all_kernel(float* __restrict__ out) {
    const int idx = blockIdx.x;
    if (idx < 128) {
        gather_body<1, 64, 160, 2, 2>(out, idx >> 6, (idx & 63) * 64);
    } else {
        const int t = idx - 128;
        gather_body<0, 128, 16, 4, 1>(out, t >> 5, (t & 31) * 128);
    }
}

// ---------------------------------------------------------------------------
extern "C" void kernel_launch(void* const* d_in, const int* in_sizes, int n_in,
                              void* d_out, int out_size) {
    const float* trg       = (const float*)d_in[0];
    const float* src       = (const float*)d_in[1];
    const float* ref       = (const float*)d_in[2];
    const float* src_feats = (const float*)d_in[3];
    const float* ref_feats = (const float*)d_in[4];
    const float* ref_sem   = (const float*)d_in[5];
    float* out = (float*)d_out;

    cudaFuncSetAttribute(corr_kernel, cudaFuncAttributeMaxDynamicSharedMemorySize, CORR_SMEM);
    cudaFuncSetAttribute(gather_all_kernel, cudaFuncAttributeMaxDynamicSharedMemorySize, GA_SMEM);

    zero_kernel<<<4 * NL / 256, 256>>>();
    norm_kernel<<<dim3(NL / 32, NB, 3), 256>>>(trg, src, ref);
    vprep_kernel<<<dim3(NL / 256, 160, 4), 256>>>(src_feats, ref_feats, ref_sem);
    corr_kernel<<<dim3(NL / 128, NL / 128, 4), 128, CORR_SMEM>>>();
    gather_all_kernel<<<192, 128, GA_SMEM>>>(out);
}

// round 9
// speedup vs baseline: 10.3409x; 1.5605x over previous
#include <cuda_runtime.h>
#include <cuda_fp16.h>
#include <cstdint>

#define NB 2
#define NC 256
#define NL 4096

// ---------------------------------------------------------------------------
// Scratch
// ---------------------------------------------------------------------------
__device__ __half g_q [NB * NL * NC];       // normalized trg, [B][L][C] K-major
__device__ __half g_ks[NB * NL * NC];
__device__ __half g_kr[NB * NL * NC];
__device__ __half g_v [4ull * 160 * NL];    // padded V banks per z

// ---------------------------------------------------------------------------
// helpers
// ---------------------------------------------------------------------------
__device__ __forceinline__ uint32_t smem_u32(const void* p) {
    uint32_t a;
    asm("{ .reg .u64 t; cvta.to.shared.u64 t, %1; cvt.u32.u64 %0, t; }" : "=r"(a) : "l"(p));
    return a;
}

#define CPA16(dst, src) asm volatile("cp.async.cg.shared.global [%0], [%1], 16;" :: "r"(dst), "l"(src))
#define CPCOMMIT()      asm volatile("cp.async.commit_group;" ::: "memory")
#define CPWAIT(n)       asm volatile("cp.async.wait_group %0;" :: "n"(n) : "memory")

#define LDSM_X4(R0, R1, R2, R3, A) \
    asm volatile("ldmatrix.sync.aligned.m8n8.x4.shared.b16 {%0,%1,%2,%3}, [%4];" \
                 : "=r"(R0), "=r"(R1), "=r"(R2), "=r"(R3) : "r"(A))

// byte offset of the 16B group (m, f) in a 128B-row tile, row-XOR swizzled
__device__ __forceinline__ uint32_t swzb(int m, int f) {
    return ((uint32_t)m << 7) + (uint32_t)(((f) ^ (m & 7)) << 4);
}

__device__ __forceinline__ void mma16(float* d, const uint32_t* a, uint32_t b0, uint32_t b1) {
    asm volatile(
        "mma.sync.aligned.m16n8k16.row.col.f32.f16.f16.f32 "
        "{%0,%1,%2,%3}, {%4,%5,%6,%7}, {%8,%9}, {%0,%1,%2,%3};"
        : "+f"(d[0]), "+f"(d[1]), "+f"(d[2]), "+f"(d[3])
        : "r"(a[0]), "r"(a[1]), "r"(a[2]), "r"(a[3]), "r"(b0), "r"(b1));
}

// ---------------------------------------------------------------------------
// Kernel 1: normalize -> [B][L][C] K-major, fp16
// ---------------------------------------------------------------------------
__global__ void __launch_bounds__(256) norm_kernel(const float* __restrict__ trg,
                                                   const float* __restrict__ src,
                                                   const float* __restrict__ ref) {
    const int which = blockIdx.z;
    const float* x = (which == 0) ? trg : (which == 1) ? src : ref;
    __half* y      = (which == 0) ? g_q : (which == 1) ? g_ks : g_kr;

    const int b = blockIdx.y;
    const int l0 = blockIdx.x * 32;
    const int t = threadIdx.x;
    const int l = t & 31;
    const int cg = t >> 5;

    __shared__ float buf[32][257];
    __shared__ float red[2][8][32];
    __shared__ float mi[2][32];

    const float* xb = x + (size_t)b * NC * NL + l0 + l;

    float s = 0.f, q = 0.f;
#pragma unroll 8
    for (int cc = 0; cc < 32; cc++) {
        const int c = cg * 32 + cc;
        float v = xb[(size_t)c * NL];
        buf[l][c] = v;
        s += v;
        q += v * v;
    }
    red[0][cg][l] = s;
    red[1][cg][l] = q;
    __syncthreads();

    if (t < 32) {
        float su = 0.f, ss = 0.f;
#pragma unroll
        for (int w = 0; w < 8; w++) { su += red[0][w][t]; ss += red[1][w][t]; }
        const float mean = su * (1.0f / NC);
        mi[0][t] = mean;
        mi[1][t] = rsqrtf(fmaxf(ss - su * mean, 1e-30f));
    }
    __syncthreads();

    const float mean = mi[0][l];
    const float inv = mi[1][l];
#pragma unroll 8
    for (int cc = 0; cc < 32; cc++) {
        const int c = cg * 32 + cc;
        buf[l][c] = (buf[l][c] - mean) * inv;
    }
    __syncthreads();

    __half* yb = y + (size_t)b * NL * NC + (size_t)l0 * NC;
#pragma unroll 8
    for (int r = 0; r < 32; r++) {
        yb[(size_t)r * NC + t] = __float2half_rn(buf[r][t]);
    }
}

// ---------------------------------------------------------------------------
// Kernel 1b: padded fp16 V banks. type0: rows 0..15. type1: rows 0..159.
// ---------------------------------------------------------------------------
__global__ void __launch_bounds__(256) vprep_kernel(const float* __restrict__ sf,
                                                    const float* __restrict__ rf,
                                                    const float* __restrict__ rs) {
    const int z = blockIdx.z, b = z & 1, type = z >> 1;
    const int n = blockIdx.y;
    if (!type && n >= 16) return;
    const int l = blockIdx.x * 256 + threadIdx.x;
    float v = 0.f;
    if (n < 4) v = (type ? rf : sf)[(size_t)b * 4 * NL + (size_t)n * NL + l];
    else if (type && n < 155) v = rs[(size_t)b * 151 * NL + (size_t)(n - 4) * NL + l];
    g_v[(size_t)z * 160 * NL + (size_t)n * NL + l] = __float2half_rn(v);
}

// ---------------------------------------------------------------------------
// Fused attention: per CTA, 128 Q-rows. Loop j-tiles of 64:
//   S = Q K^T (K=256), e = exp(S) in regs, O += e * V^T (FA2 frag reuse),
//   rsum accumulated in regs. Final: out = O / rsum.
// 256 threads = 8 warps; warp w owns rows w*16..w*16+15, full N channels.
// smem: Q 128x256 fp16 persistent (4 blocks of 128B rows) + 3-stage K tile
// (64x256) + 3-stage V tile (NCH x 64).
// ---------------------------------------------------------------------------
#define QOFF   0u
#define KOFF   65536u
#define KSTG   32768u
#define VOFF   (65536u + 3u * 32768u)       // 163840
#define ATTN_SMEM (163840 + 3 * 160 * 128)  // 225280

extern __shared__ char g_dsm[];

template <int TYPE, int NCH>
__device__ __forceinline__ void attn_body(float* __restrict__ out, int b, int i0) {
    constexpr int NT2 = NCH / 16;           // V x4-ldmatrix groups (10 or 1)
    constexpr int NO  = NCH / 8;            // O n-tiles (20 or 2)
    constexpr uint32_t VSZ = NCH * 128;

    const int tid = threadIdx.x, lane = tid & 31, w = tid >> 5;
    const int z = TYPE * 2 + b;

    const __half* __restrict__ Qp = g_q + (size_t)b * NL * NC;
    const __half* __restrict__ Kp = (TYPE ? g_kr : g_ks) + (size_t)b * NL * NC;
    const __half* __restrict__ Vp = g_v + (size_t)z * 160 * NL;

    const uint32_t sb = smem_u32(g_dsm);

    // ---- loaders ----
    auto load_q = [&]() {
#pragma unroll
        for (int it = 0; it < 16; it++) {
            int idx = tid + it * 256;
            int m = idx >> 5, rem = idx & 31, kb = rem >> 3, f = rem & 7;
            CPA16(sb + QOFF + kb * 16384u + swzb(m, f),
                  Qp + (size_t)(i0 + m) * NC + kb * 64 + f * 8);
        }
    };
    auto stage_kv = [&](int st, int j0) {
        const uint32_t kbase = sb + KOFF + (uint32_t)st * KSTG;
#pragma unroll
        for (int it = 0; it < 8; it++) {
            int idx = tid + it * 256;
            int m = idx >> 5, rem = idx & 31, kb = rem >> 3, f = rem & 7;
            CPA16(kbase + kb * 8192u + swzb(m, f),
                  Kp + (size_t)(j0 + m) * NC + kb * 64 + f * 8);
        }
        const uint32_t vbase = sb + VOFF + (uint32_t)st * VSZ;
        for (int idx = tid; idx < NCH * 8; idx += 256) {
            int n = idx >> 3, f = idx & 7;
            CPA16(vbase + swzb(n, f), Vp + (size_t)n * NL + j0 + f * 8);
        }
    };

    // ---- lane geometry ----
    const int arow = ((lane >> 3) & 1) * 8 + (lane & 7);
    const int a_fb = lane >> 4;
    const int m_row = w * 16 + arow;
    const uint32_t a_off = (uint32_t)m_row << 7;
    const int a_x = arow & 7;

    const int brow = ((lane >> 4) & 1) * 8 + (lane & 7);
    const int b_fb = (lane >> 3) & 1;
    const uint32_t b_off = (uint32_t)brow << 7;
    const int b_x = brow & 7;

    float oacc[NO][4];
#pragma unroll
    for (int nt = 0; nt < NO; nt++)
#pragma unroll
        for (int k = 0; k < 4; k++) oacc[nt][k] = 0.f;
    float rs0 = 0.f, rs1 = 0.f;

    load_q();
    stage_kv(0, 0);
    CPCOMMIT();
    stage_kv(1, 64);
    CPCOMMIT();

    int buf = 0;
    for (int c = 0; c < 64; c++) {
        if (c < 63) { CPWAIT(1); } else { CPWAIT(0); }
        __syncthreads();
        const uint32_t Kb = sb + KOFF + (uint32_t)buf * KSTG;
        const uint32_t Vb = sb + VOFF + (uint32_t)buf * VSZ;

        // ---- S = Q K^T over K=256 ----
        float s[8][4];
#pragma unroll
        for (int nt = 0; nt < 8; nt++)
#pragma unroll
            for (int k = 0; k < 4; k++) s[nt][k] = 0.f;

#pragma unroll
        for (int ks = 0; ks < 16; ks++) {
            const int kb = ks >> 2, ff = (ks & 3) * 2;
            uint32_t a[4];
            {
                const int f = ff + a_fb;
                LDSM_X4(a[0], a[1], a[2], a[3],
                        sb + QOFF + kb * 16384u + a_off + (uint32_t)((f ^ a_x) << 4));
            }
#pragma unroll
            for (int nt2 = 0; nt2 < 4; nt2++) {
                uint32_t bb[4];
                const int f = ff + b_fb;
                LDSM_X4(bb[0], bb[1], bb[2], bb[3],
                        Kb + kb * 8192u + (uint32_t)(nt2 << 11) + b_off + (uint32_t)((f ^ b_x) << 4));
                mma16(s[nt2 * 2],     a, bb[0], bb[1]);
                mma16(s[nt2 * 2 + 1], a, bb[2], bb[3]);
            }
        }

        // ---- exp + row-sum accumulation ----
#pragma unroll
        for (int nt = 0; nt < 8; nt++) {
            s[nt][0] = __expf(s[nt][0]);
            s[nt][1] = __expf(s[nt][1]);
            s[nt][2] = __expf(s[nt][2]);
            s[nt][3] = __expf(s[nt][3]);
            rs0 += s[nt][0] + s[nt][1];
            rs1 += s[nt][2] + s[nt][3];
        }

        // ---- O += e * V^T : S-acc frags become A frags (FA2 identity) ----
#pragma unroll
        for (int kk = 0; kk < 4; kk++) {
            uint32_t af[4];
            af[0] = __half2half2(__half(0)).x;  // placeholder overwritten below
            {
                __half2 h;
                h = __floats2half2_rn(s[2 * kk][0], s[2 * kk][1]);     af[0] = *(uint32_t*)&h;
                h = __floats2half2_rn(s[2 * kk][2], s[2 * kk][3]);     af[1] = *(uint32_t*)&h;
                h = __floats2half2_rn(s[2 * kk + 1][0], s[2 * kk + 1][1]); af[2] = *(uint32_t*)&h;
                h = __floats2half2_rn(s[2 * kk + 1][2], s[2 * kk + 1][3]); af[3] = *(uint32_t*)&h;
            }
#pragma unroll
            for (int nt2 = 0; nt2 < NT2; nt2++) {
                uint32_t bb[4];
                const int f = 2 * kk + b_fb;
                LDSM_X4(bb[0], bb[1], bb[2], bb[3],
                        Vb + (uint32_t)(nt2 << 11) + b_off + (uint32_t)((f ^ b_x) << 4));
                mma16(oacc[nt2 * 2],     af, bb[0], bb[1]);
                mma16(oacc[nt2 * 2 + 1], af, bb[2], bb[3]);
            }
        }

        if (c < 62) {
            int nb = buf + 2; if (nb >= 3) nb -= 3;
            stage_kv(nb, (c + 2) * 64);
            CPCOMMIT();
        }
        if (++buf == 3) buf = 0;
    }

    // ---- epilogue: normalize and write ----
    const int q = lane & 3, r = lane >> 2;
    rs0 += __shfl_xor_sync(0xffffffffu, rs0, 1);
    rs0 += __shfl_xor_sync(0xffffffffu, rs0, 2);
    rs1 += __shfl_xor_sync(0xffffffffu, rs1, 1);
    rs1 += __shfl_xor_sync(0xffffffffu, rs1, 2);
    const float inv0 = 1.0f / rs0;
    const float inv1 = 1.0f / rs1;

    float* Of = TYPE ? (out + 2 * 4 * NL + (size_t)b * 4 * NL)
                     : (out + (size_t)b * 4 * NL);
    float* Os = out + 4 * 4 * NL + (size_t)b * 151 * NL;

    const int row = i0 + w * 16 + r;
#pragma unroll
    for (int nt = 0; nt < NO; nt++) {
        const int cbase = nt * 8 + 2 * q;
#pragma unroll
        for (int hh = 0; hh < 2; hh++) {
            const int i = row + hh * 8;
            const float inv = hh ? inv1 : inv0;
#pragma unroll
            for (int dd = 0; dd < 2; dd++) {
                const int cch = cbase + dd;
                const float val = oacc[nt][hh * 2 + dd] * inv;
                if (cch < 4) Of[(size_t)cch * NL + i] = val;
                else if (TYPE && cch < 155) Os[(size_t)(cch - 4) * NL + i] = val;
            }
        }
    }
}

__global__ void __launch_bounds__(256, 1) attn_kernel(float* __restrict__ out) {
    const int idx = blockIdx.x;
    if (idx < 64) {
        attn_body<1, 160>(out, idx >> 5, (idx & 31) * 128);
    } else {
        const int t = idx - 64;
        attn_body<0, 16>(out, t >> 5, (t & 31) * 128);
    }
}

// ---------------------------------------------------------------------------
extern "C" void kernel_launch(void* const* d_in, const int* in_sizes, int n_in,
                              void* d_out, int out_size) {
    const float* trg       = (const float*)d_in[0];
    const float* src       = (const float*)d_in[1];
    const float* ref       = (const float*)d_in[2];
    const float* src_feats = (const float*)d_in[3];
    const float* ref_feats = (const float*)d_in[4];
    const float* ref_sem   = (const float*)d_in[5];
    float* out = (float*)d_out;

    cudaFuncSetAttribute(attn_kernel, cudaFuncAttributeMaxDynamicSharedMemorySize, ATTN_SMEM);

    norm_kernel<<<dim3(NL / 32, NB, 3), 256>>>(trg, src, ref);
    vprep_kernel<<<dim3(NL / 256, 160, 4), 256>>>(src_feats, ref_feats, ref_sem);
    attn_kernel<<<128, 256, ATTN_SMEM>>>(out);
}